// round 14
// baseline (speedup 1.0000x reference)
#include <cuda_runtime.h>
#include <cuda_bf16.h>
#include <cuda_fp16.h>
#include <math.h>
#include <stdint.h>

// ---------------- problem constants ----------------
#define BATCH 4
#define SEQ 4096
#define DMODEL 1024
#define NHEAD 16
#define DH 64
#define MTOK (BATCH*SEQ)   // 16384
#define ACT_ELEMS ((size_t)MTOK * DMODEL)
#define W_ELEMS   ((size_t)DMODEL * DMODEL)

// ---------------- scratch (__device__ globals; allocation-free rule) ------
__device__ float g_q [ACT_ELEMS];
__device__ float g_k [ACT_ELEMS];
__device__ float g_v [ACT_ELEMS];
// slice 0: Q acts bf16-hi (later reused as ao fp16), 1: K acts bf16-hi, 2: V acts fp16
__device__ __nv_bfloat16 g_xh[3 * ACT_ELEMS];
__device__ __nv_bfloat16 g_xl[3 * ACT_ELEMS];   // lo splits for slices 0,1 only
// slice 0: Wq-hi bf16, 1: Wk-hi bf16, 2: Wv fp16 (single), 3: Wo fp16 (single)
__device__ __nv_bfloat16 g_wh[4 * W_ELEMS];
__device__ __nv_bfloat16 g_wl[4 * W_ELEMS];     // lo used only for slices 0,1

// ---------------- small PTX helpers (base ISA only) ----------------
__device__ __forceinline__ uint32_t smem_u32(const void* p) {
    uint32_t a;
    asm("{ .reg .u64 t; cvta.to.shared.u64 t, %1; cvt.u32.u64 %0, t; }" : "=r"(a) : "l"(p));
    return a;
}

#define CP_ASYNC16(saddr, gptr) \
    asm volatile("cp.async.cg.shared.global [%0], [%1], 16;" :: "r"((uint32_t)(saddr)), "l"(gptr))
#define CP_COMMIT() asm volatile("cp.async.commit_group;" ::: "memory")
#define CP_WAIT(n)  asm volatile("cp.async.wait_group %0;" :: "n"(n) : "memory")

#define LDSM_X4(r, addr) \
    asm volatile("ldmatrix.sync.aligned.m8n8.x4.shared.b16 {%0,%1,%2,%3}, [%4];" \
        : "=r"((r)[0]), "=r"((r)[1]), "=r"((r)[2]), "=r"((r)[3]) : "r"(addr))

__device__ __forceinline__ void mma16816(float* d, const uint32_t* a, const uint32_t* b) {
    asm volatile(
        "mma.sync.aligned.m16n8k16.row.col.f32.bf16.bf16.f32 "
        "{%0,%1,%2,%3}, {%4,%5,%6,%7}, {%8,%9}, {%0,%1,%2,%3};"
        : "+f"(d[0]), "+f"(d[1]), "+f"(d[2]), "+f"(d[3])
        : "r"(a[0]), "r"(a[1]), "r"(a[2]), "r"(a[3]), "r"(b[0]), "r"(b[1]));
}

__device__ __forceinline__ void mma16816h(float* d, const uint32_t* a, const uint32_t* b) {
    asm volatile(
        "mma.sync.aligned.m16n8k16.row.col.f32.f16.f16.f32 "
        "{%0,%1,%2,%3}, {%4,%5,%6,%7}, {%8,%9}, {%0,%1,%2,%3};"
        : "+f"(d[0]), "+f"(d[1]), "+f"(d[2]), "+f"(d[3])
        : "r"(a[0]), "r"(a[1]), "r"(a[2]), "r"(a[3]), "r"(b[0]), "r"(b[1]));
}

// ---------------- splits ----------------
__device__ __forceinline__ void split4_bf16(float4 x, uint2& H, uint2& L) {
    __nv_bfloat162 h01 = __floats2bfloat162_rn(x.x, x.y);
    __nv_bfloat162 h23 = __floats2bfloat162_rn(x.z, x.w);
    float2 f01 = __bfloat1622float2(h01);
    float2 f23 = __bfloat1622float2(h23);
    __nv_bfloat162 l01 = __floats2bfloat162_rn(x.x - f01.x, x.y - f01.y);
    __nv_bfloat162 l23 = __floats2bfloat162_rn(x.z - f23.x, x.w - f23.y);
    H.x = *reinterpret_cast<unsigned int*>(&h01);
    H.y = *reinterpret_cast<unsigned int*>(&h23);
    L.x = *reinterpret_cast<unsigned int*>(&l01);
    L.y = *reinterpret_cast<unsigned int*>(&l23);
}

__device__ __forceinline__ uint2 pack4_f16(float4 x) {
    __half2 h01 = __floats2half2_rn(x.x, x.y);
    __half2 h23 = __floats2half2_rn(x.z, x.w);
    uint2 H;
    H.x = *reinterpret_cast<unsigned int*>(&h01);
    H.y = *reinterpret_cast<unsigned int*>(&h23);
    return H;
}

// acts: y=0 query (bf16 split), y=1 key_ (bf16 split), y=2 value (fp16 single)
__global__ void __launch_bounds__(256) split_acts_kernel(
    const float4* __restrict__ s0, const float4* __restrict__ s1, const float4* __restrict__ s2,
    uint2* __restrict__ hi, uint2* __restrict__ lo, int n4)
{
    int i = blockIdx.x * blockDim.x + threadIdx.x;
    if (i >= n4) return;
    int which = blockIdx.y;
    if (which < 2) {
        uint2 H, L;
        split4_bf16(which == 0 ? s0[i] : s1[i], H, L);
        hi[(size_t)which * n4 + i] = H;
        lo[(size_t)which * n4 + i] = L;
    } else {
        hi[(size_t)2 * n4 + i] = pack4_f16(s2[i]);
    }
}

// weights: y=0 Wq / y=1 Wk bf16 split; y=2 Wv / y=3 Wo fp16 single (hi only)
__global__ void __launch_bounds__(256) split_w_kernel(
    const float4* __restrict__ s0, const float4* __restrict__ s1,
    const float4* __restrict__ s2, const float4* __restrict__ s3,
    uint2* __restrict__ hi, uint2* __restrict__ lo, int n4)
{
    int i = blockIdx.x * blockDim.x + threadIdx.x;
    if (i >= n4) return;
    int which = blockIdx.y;
    if (which < 2) {
        uint2 H, L;
        split4_bf16(which == 0 ? s0[i] : s1[i], H, L);
        hi[(size_t)which * n4 + i] = H;
        lo[(size_t)which * n4 + i] = L;
    } else {
        hi[(size_t)which * n4 + i] = pack4_f16(which == 2 ? s2[i] : s3[i]);
    }
}

// ================= bf16x3 GEMM (GBK64, 1 CTA/SM) — R9 config ==============
#define GBM 128
#define GBN 128
#define GBK 64
#define KDIM DMODEL
#define NCHUNK (KDIM/GBK)      // 16
#define STAGE_BYTES 65536      // Ah 16K | Al 16K | Bh 16K | Bl 16K
#define A_HI 0
#define A_LO 16384
#define B_HI 32768
#define B_LO 49152
#define NSTAGE 3
#define GSMEM_TOTAL (NSTAGE*STAGE_BYTES)   // 196608

__global__ void __launch_bounds__(256, 1) gemm_bf16x3(
    const __nv_bfloat16* __restrict__ Ah, const __nv_bfloat16* __restrict__ Al,
    const __nv_bfloat16* __restrict__ Wh, const __nv_bfloat16* __restrict__ Wl,
    const float* __restrict__ bias, float* __restrict__ C)
{
    extern __shared__ char smem[];
    const uint32_t sb = smem_u32(smem);
    const int tid = threadIdx.x;
    const int m0 = blockIdx.y * GBM;
    const int n0 = blockIdx.x * GBN;

    const int l  = tid & 31;
    const int w  = tid >> 5;
    const int wm = (w & 3) * 32;
    const int wn = (w >> 2) * 64;

    const int rowA  = (l & 7) + ((l >> 3) & 1) * 8;
    const int kselA = (l >> 4) & 1;
    const int rowB  = (l & 7) + ((l >> 4) & 1) * 8;
    const int kselB = (l >> 3) & 1;

    float acc[2][8][4];
#pragma unroll
    for (int a = 0; a < 2; a++)
#pragma unroll
        for (int b = 0; b < 8; b++)
#pragma unroll
            for (int c = 0; c < 4; c++) acc[a][b][c] = 0.0f;

    auto load_chunk = [&](int st, int c) {
        uint32_t base = sb + st * STAGE_BYTES;
        int k0 = c * GBK;
#pragma unroll
        for (int it = 0; it < 4; it++) {
            int idx = tid + it * 256;
            int r  = idx >> 3;
            int ch = idx & 7;
            uint32_t sw = (uint32_t)(r * 128 + ((ch ^ (r & 7)) * 16));
            size_t gA = (size_t)(m0 + r) * KDIM + k0 + ch * 8;
            size_t gB = (size_t)(n0 + r) * KDIM + k0 + ch * 8;
            CP_ASYNC16(base + A_HI + sw, Ah + gA);
            CP_ASYNC16(base + A_LO + sw, Al + gA);
            CP_ASYNC16(base + B_HI + sw, Wh + gB);
            CP_ASYNC16(base + B_LO + sw, Wl + gB);
        }
    };

    uint32_t a_h[2][2][4], a_l[2][2][4], b_h[2][4][4], b_l[2][4][4];

    auto load_step = [&](uint32_t base, int s, int buf) {
#pragma unroll
        for (int mt = 0; mt < 2; mt++) {
            int row = wm + mt * 16 + rowA;
            int ch  = (s * 2 + kselA) ^ (row & 7);
            uint32_t off = (uint32_t)(row * 128 + ch * 16);
            LDSM_X4(a_h[buf][mt], base + A_HI + off);
            LDSM_X4(a_l[buf][mt], base + A_LO + off);
        }
#pragma unroll
        for (int ng = 0; ng < 4; ng++) {
            int row = wn + ng * 16 + rowB;
            int ch  = (s * 2 + kselB) ^ (row & 7);
            uint32_t off = (uint32_t)(row * 128 + ch * 16);
            LDSM_X4(b_h[buf][ng], base + B_HI + off);
            LDSM_X4(b_l[buf][ng], base + B_LO + off);
        }
    };

    auto mma_step = [&](int buf) {
#pragma unroll
        for (int p = 0; p < 3; p++) {
#pragma unroll
            for (int mt = 0; mt < 2; mt++) {
#pragma unroll
                for (int ng = 0; ng < 4; ng++) {
                    const uint32_t* A = (p == 2) ? a_l[buf][mt] : a_h[buf][mt];
                    const uint32_t* B = (p == 1) ? b_l[buf][ng] : b_h[buf][ng];
                    mma16816(acc[mt][ng * 2 + 0], A, &B[0]);
                    mma16816(acc[mt][ng * 2 + 1], A, &B[2]);
                }
            }
        }
    };

    load_chunk(0, 0); CP_COMMIT();
    load_chunk(1, 1); CP_COMMIT();

    for (int c = 0; c < NCHUNK; c++) {
        int st = c % NSTAGE;
        uint32_t base = sb + st * STAGE_BYTES;
        if (c + 2 < NCHUNK) { CP_WAIT(1); } else { CP_WAIT(0); }
        __syncthreads();
        if (c + 2 < NCHUNK) {
            load_chunk((c + 2) % NSTAGE, c + 2); CP_COMMIT();
        }
        load_step(base, 0, 0);
#pragma unroll
        for (int s = 0; s < 4; s++) {
            if (s < 3) load_step(base, s + 1, (s + 1) & 1);
            mma_step(s & 1);
        }
    }

    const int g  = l >> 2;
    const int tg = l & 3;
#pragma unroll
    for (int mt = 0; mt < 2; mt++) {
#pragma unroll
        for (int nt = 0; nt < 8; nt++) {
            int n = n0 + wn + nt * 8 + tg * 2;
            float bx = bias[n], by = bias[n + 1];
            int mA = m0 + wm + mt * 16 + g;
            float2 lo = make_float2(acc[mt][nt][0] + bx, acc[mt][nt][1] + by);
            float2 hi = make_float2(acc[mt][nt][2] + bx, acc[mt][nt][3] + by);
            *(float2*)(C + (size_t)mA * DMODEL + n)       = lo;
            *(float2*)(C + (size_t)(mA + 8) * DMODEL + n) = hi;
        }
    }
}

// ================= fp16x1 GEMM: C = A @ W^T + bias (V/O projections) ======
#define H1STAGE_BYTES 32768    // A 16K | B 16K
#define H1_A 0
#define H1_B 16384
#define H1SMEM_TOTAL (NSTAGE*H1STAGE_BYTES)  // 98304

__global__ void __launch_bounds__(256, 1) gemm_fp16x1(
    const __half* __restrict__ A, const __half* __restrict__ W,
    const float* __restrict__ bias, float* __restrict__ C)
{
    extern __shared__ char smem[];
    const uint32_t sb = smem_u32(smem);
    const int tid = threadIdx.x;
    const int m0 = blockIdx.y * GBM;
    const int n0 = blockIdx.x * GBN;

    const int l  = tid & 31;
    const int w  = tid >> 5;
    const int wm = (w & 3) * 32;
    const int wn = (w >> 2) * 64;

    const int rowA  = (l & 7) + ((l >> 3) & 1) * 8;
    const int kselA = (l >> 4) & 1;
    const int rowB  = (l & 7) + ((l >> 4) & 1) * 8;
    const int kselB = (l >> 3) & 1;

    float acc[2][8][4];
#pragma unroll
    for (int a = 0; a < 2; a++)
#pragma unroll
        for (int b = 0; b < 8; b++)
#pragma unroll
            for (int c = 0; c < 4; c++) acc[a][b][c] = 0.0f;

    auto load_chunk = [&](int st, int c) {
        uint32_t base = sb + st * H1STAGE_BYTES;
        int k0 = c * GBK;
#pragma unroll
        for (int it = 0; it < 4; it++) {
            int idx = tid + it * 256;
            int r  = idx >> 3;
            int ch = idx & 7;
            uint32_t sw = (uint32_t)(r * 128 + ((ch ^ (r & 7)) * 16));
            size_t gA = (size_t)(m0 + r) * KDIM + k0 + ch * 8;
            size_t gB = (size_t)(n0 + r) * KDIM + k0 + ch * 8;
            CP_ASYNC16(base + H1_A + sw, A + gA);
            CP_ASYNC16(base + H1_B + sw, W + gB);
        }
    };

    load_chunk(0, 0); CP_COMMIT();
    load_chunk(1, 1); CP_COMMIT();

    uint32_t ra[2][4], rb[4][4];

    for (int c = 0; c < NCHUNK; c++) {
        int st = c % NSTAGE;
        uint32_t base = sb + st * H1STAGE_BYTES;
        if (c + 2 < NCHUNK) { CP_WAIT(1); } else { CP_WAIT(0); }
        __syncthreads();
        if (c + 2 < NCHUNK) {
            load_chunk((c + 2) % NSTAGE, c + 2); CP_COMMIT();
        }
#pragma unroll
        for (int s = 0; s < 4; s++) {
#pragma unroll
            for (int mt = 0; mt < 2; mt++) {
                int row = wm + mt * 16 + rowA;
                int ch  = (s * 2 + kselA) ^ (row & 7);
                LDSM_X4(ra[mt], base + H1_A + (uint32_t)(row * 128 + ch * 16));
            }
#pragma unroll
            for (int ng = 0; ng < 4; ng++) {
                int row = wn + ng * 16 + rowB;
                int ch  = (s * 2 + kselB) ^ (row & 7);
                LDSM_X4(rb[ng], base + H1_B + (uint32_t)(row * 128 + ch * 16));
            }
#pragma unroll
            for (int mt = 0; mt < 2; mt++)
#pragma unroll
                for (int ng = 0; ng < 4; ng++) {
                    mma16816h(acc[mt][ng * 2 + 0], ra[mt], &rb[ng][0]);
                    mma16816h(acc[mt][ng * 2 + 1], ra[mt], &rb[ng][2]);
                }
        }
    }

    const int g  = l >> 2;
    const int tg = l & 3;
#pragma unroll
    for (int mt = 0; mt < 2; mt++) {
#pragma unroll
        for (int nt = 0; nt < 8; nt++) {
            int n = n0 + wn + nt * 8 + tg * 2;
            float bx = bias[n], by = bias[n + 1];
            int mA = m0 + wm + mt * 16 + g;
            float2 lo = make_float2(acc[mt][nt][0] + bx, acc[mt][nt][1] + by);
            float2 hi = make_float2(acc[mt][nt][2] + bx, acc[mt][nt][3] + by);
            *(float2*)(C + (size_t)mA * DMODEL + n)       = lo;
            *(float2*)(C + (size_t)(mA + 8) * DMODEL + n) = hi;
        }
    }
}

// ---------------- per-token attention v2 ----------------------------------
// One warp per token (4 tokens / 128-thread block); lane owns rows l and l+32.
// k/v smem is warp-private => __syncwarp only. Output: single fp16.
__global__ __launch_bounds__(128) void attn_per_token(
    const float* __restrict__ q, const float* __restrict__ k,
    const float* __restrict__ v, __half* __restrict__ ao)
{
    const int w = threadIdx.x >> 5;
    const int l = threadIdx.x & 31;
    const int t = blockIdx.x * 4 + w;

    __shared__ float sk[4][DMODEL];
    __shared__ float sv[4][DMODEL];

    const float4* kt = (const float4*)(k + (size_t)t * DMODEL);
    const float4* vt = (const float4*)(v + (size_t)t * DMODEL);
    float4* skw = (float4*)sk[w];
    float4* svw = (float4*)sv[w];
#pragma unroll
    for (int f = l; f < 256; f += 32) {
        skw[f] = kt[f];
        svw[f] = vt[f];
    }
    __syncwarp();

    // two q rows per lane, pre-scaled by 32 (the *sqrt(D) faithful quirk)
    float4 q0[4], q1[4];
    const float4* qt0 = (const float4*)(q + (size_t)t * DMODEL + l * NHEAD);
    const float4* qt1 = (const float4*)(q + (size_t)t * DMODEL + (l + 32) * NHEAD);
#pragma unroll
    for (int hg = 0; hg < 4; hg++) {
        float4 a = qt0[hg], b = qt1[hg];
        q0[hg] = make_float4(a.x * 32.f, a.y * 32.f, a.z * 32.f, a.w * 32.f);
        q1[hg] = make_float4(b.x * 32.f, b.y * 32.f, b.z * 32.f, b.w * 32.f);
    }

    float m0 = -1e30f, m1 = -1e30f, s0 = 0.f, s1 = 0.f;
    float4 o0[4], o1[4];
#pragma unroll
    for (int hg = 0; hg < 4; hg++) {
        o0[hg] = make_float4(0.f, 0.f, 0.f, 0.f);
        o1[hg] = make_float4(0.f, 0.f, 0.f, 0.f);
    }

#pragma unroll
    for (int jc = 0; jc < 4; jc++) {
        float sA[16], sB[16];
        float c0 = -1e30f, c1 = -1e30f;
#pragma unroll
        for (int jj = 0; jj < 16; jj++) {
            int j = jc * 16 + jj;
            float a0 = 0.f, a1 = 0.f;
#pragma unroll
            for (int hg = 0; hg < 4; hg++) {
                float4 kk = skw[j * 4 + hg];
                a0 = fmaf(q0[hg].x, kk.x, a0); a0 = fmaf(q0[hg].y, kk.y, a0);
                a0 = fmaf(q0[hg].z, kk.z, a0); a0 = fmaf(q0[hg].w, kk.w, a0);
                a1 = fmaf(q1[hg].x, kk.x, a1); a1 = fmaf(q1[hg].y, kk.y, a1);
                a1 = fmaf(q1[hg].z, kk.z, a1); a1 = fmaf(q1[hg].w, kk.w, a1);
            }
            sA[jj] = a0; sB[jj] = a1;
            c0 = fmaxf(c0, a0); c1 = fmaxf(c1, a1);
        }
        float n0 = fmaxf(m0, c0), n1 = fmaxf(m1, c1);
        float r0 = __expf(m0 - n0), r1 = __expf(m1 - n1);
        s0 *= r0; s1 *= r1;
#pragma unroll
        for (int hg = 0; hg < 4; hg++) {
            o0[hg].x *= r0; o0[hg].y *= r0; o0[hg].z *= r0; o0[hg].w *= r0;
            o1[hg].x *= r1; o1[hg].y *= r1; o1[hg].z *= r1; o1[hg].w *= r1;
        }
#pragma unroll
        for (int jj = 0; jj < 16; jj++) {
            int j = jc * 16 + jj;
            float p0 = __expf(sA[jj] - n0);
            float p1 = __expf(sB[jj] - n1);
            s0 += p0; s1 += p1;
#pragma unroll
            for (int hg = 0; hg < 4; hg++) {
                float4 vv = svw[j * 4 + hg];
                o0[hg].x = fmaf(p0, vv.x, o0[hg].x); o0[hg].y = fmaf(p0, vv.y, o0[hg].y);
                o0[hg].z = fmaf(p0, vv.z, o0[hg].z); o0[hg].w = fmaf(p0, vv.w, o0[hg].w);
                o1[hg].x = fmaf(p1, vv.x, o1[hg].x); o1[hg].y = fmaf(p1, vv.y, o1[hg].y);
                o1[hg].z = fmaf(p1, vv.z, o1[hg].z); o1[hg].w = fmaf(p1, vv.w, o1[hg].w);
            }
        }
        m0 = n0; m1 = n1;
    }

    const float i0 = 1.0f / s0;
    const float i1 = 1.0f / s1;
    uint32_t h0[8], h1[8];
#pragma unroll
    for (int hg = 0; hg < 4; hg++) {
        __half2 a0 = __floats2half2_rn(o0[hg].x * i0, o0[hg].y * i0);
        __half2 b0 = __floats2half2_rn(o0[hg].z * i0, o0[hg].w * i0);
        __half2 a1 = __floats2half2_rn(o1[hg].x * i1, o1[hg].y * i1);
        __half2 b1 = __floats2half2_rn(o1[hg].z * i1, o1[hg].w * i1);
        h0[hg * 2 + 0] = *reinterpret_cast<uint32_t*>(&a0);
        h0[hg * 2 + 1] = *reinterpret_cast<uint32_t*>(&b0);
        h1[hg * 2 + 0] = *reinterpret_cast<uint32_t*>(&a1);
        h1[hg * 2 + 1] = *reinterpret_cast<uint32_t*>(&b1);
    }
    size_t ob0 = (size_t)t * DMODEL + l * NHEAD;
    size_t ob1 = (size_t)t * DMODEL + (l + 32) * NHEAD;
    *(uint4*)(ao + ob0)     = make_uint4(h0[0], h0[1], h0[2], h0[3]);
    *(uint4*)(ao + ob0 + 8) = make_uint4(h0[4], h0[5], h0[6], h0[7]);
    *(uint4*)(ao + ob1)     = make_uint4(h1[0], h1[1], h1[2], h1[3]);
    *(uint4*)(ao + ob1 + 8) = make_uint4(h1[4], h1[5], h1[6], h1[7]);
}

// ---------------- launch ----------------
extern "C" void kernel_launch(void* const* d_in, const int* in_sizes, int n_in,
                              void* d_out, int out_size)
{
    const float* query = (const float*)d_in[0];
    const float* key_  = (const float*)d_in[1];
    const float* value = (const float*)d_in[2];
    const float* Wq    = (const float*)d_in[3];
    const float* bq    = (const float*)d_in[4];
    const float* Wk    = (const float*)d_in[5];
    const float* bk    = (const float*)d_in[6];
    const float* Wv    = (const float*)d_in[7];
    const float* bv    = (const float*)d_in[8];
    const float* Wo    = (const float*)d_in[9];
    const float* bo    = (const float*)d_in[10];
    float* out = (float*)d_out;

    float *q, *k, *v;
    __nv_bfloat16 *xh, *xl, *wh, *wl;
    cudaGetSymbolAddress((void**)&q,  g_q);
    cudaGetSymbolAddress((void**)&k,  g_k);
    cudaGetSymbolAddress((void**)&v,  g_v);
    cudaGetSymbolAddress((void**)&xh, g_xh);
    cudaGetSymbolAddress((void**)&xl, g_xl);
    cudaGetSymbolAddress((void**)&wh, g_wh);
    cudaGetSymbolAddress((void**)&wl, g_wl);

    cudaFuncSetAttribute(gemm_bf16x3, cudaFuncAttributeMaxDynamicSharedMemorySize, GSMEM_TOTAL);
    cudaFuncSetAttribute(gemm_fp16x1, cudaFuncAttributeMaxDynamicSharedMemorySize, H1SMEM_TOTAL);

    const int nAct4 = (int)(ACT_ELEMS / 4);
    const int nW4   = (int)(W_ELEMS / 4);
    dim3 sgA((nAct4 + 255) / 256, 3);
    dim3 sgW((nW4 + 255) / 256, 4);
    dim3 ggrid(DMODEL / GBN, MTOK / GBM);   // (8, 128)

    split_acts_kernel<<<sgA, 256>>>((const float4*)query, (const float4*)key_,
                                    (const float4*)value, (uint2*)xh, (uint2*)xl, nAct4);
    split_w_kernel<<<sgW, 256>>>((const float4*)Wq, (const float4*)Wk,
                                 (const float4*)Wv, (const float4*)Wo,
                                 (uint2*)wh, (uint2*)wl, nW4);

    // Q, K projections: bf16x3 (score-critical precision)
    gemm_bf16x3<<<ggrid, 256, GSMEM_TOTAL>>>(xh,             xl,             wh,           wl,           bq, q);
    gemm_bf16x3<<<ggrid, 256, GSMEM_TOTAL>>>(xh + ACT_ELEMS, xl + ACT_ELEMS, wh + W_ELEMS, wl + W_ELEMS, bk, k);
    // V projection: fp16 single product
    gemm_fp16x1<<<ggrid, 256, H1SMEM_TOTAL>>>((const __half*)(xh + 2 * ACT_ELEMS),
                                              (const __half*)(wh + 2 * W_ELEMS), bv, v);

    // attention: one warp per token, writes ao fp16 into slice 0 of xh
    attn_per_token<<<MTOK / 4, 128>>>(q, k, v, (__half*)xh);

    // O projection: fp16 single product
    gemm_fp16x1<<<ggrid, 256, H1SMEM_TOTAL>>>((const __half*)xh,
                                              (const __half*)(wh + 3 * W_ELEMS), bo, out);
}

// round 15
// speedup vs baseline: 1.0029x; 1.0029x over previous
#include <cuda_runtime.h>
#include <cuda_bf16.h>
#include <cuda_fp16.h>
#include <math.h>
#include <stdint.h>

// ---------------- problem constants ----------------
#define BATCH 4
#define SEQ 4096
#define DMODEL 1024
#define NHEAD 16
#define DH 64
#define MTOK (BATCH*SEQ)   // 16384
#define ACT_ELEMS ((size_t)MTOK * DMODEL)
#define W_ELEMS   ((size_t)DMODEL * DMODEL)

// ---------------- scratch (__device__ globals; allocation-free rule) ------
__device__ float g_q [ACT_ELEMS];
__device__ float g_k [ACT_ELEMS];
__device__ float g_v [ACT_ELEMS];
// slice 0: Q acts bf16-hi (later reused as ao fp16), 1: K acts bf16-hi, 2: V acts fp16
__device__ __nv_bfloat16 g_xh[3 * ACT_ELEMS];
__device__ __nv_bfloat16 g_xl[3 * ACT_ELEMS];   // lo splits for slices 0,1 only
// slice 0: Wq-hi bf16, 1: Wk-hi bf16, 2: Wv fp16 (single), 3: Wo fp16 (single)
__device__ __nv_bfloat16 g_wh[4 * W_ELEMS];
__device__ __nv_bfloat16 g_wl[4 * W_ELEMS];     // lo used only for slices 0,1

// ---------------- small PTX helpers (base ISA + sm_100-family f32x2) ------
__device__ __forceinline__ uint32_t smem_u32(const void* p) {
    uint32_t a;
    asm("{ .reg .u64 t; cvta.to.shared.u64 t, %1; cvt.u32.u64 %0, t; }" : "=r"(a) : "l"(p));
    return a;
}

#define CP_ASYNC16(saddr, gptr) \
    asm volatile("cp.async.cg.shared.global [%0], [%1], 16;" :: "r"((uint32_t)(saddr)), "l"(gptr))
#define CP_COMMIT() asm volatile("cp.async.commit_group;" ::: "memory")
#define CP_WAIT(n)  asm volatile("cp.async.wait_group %0;" :: "n"(n) : "memory")

#define LDSM_X4(r, addr) \
    asm volatile("ldmatrix.sync.aligned.m8n8.x4.shared.b16 {%0,%1,%2,%3}, [%4];" \
        : "=r"((r)[0]), "=r"((r)[1]), "=r"((r)[2]), "=r"((r)[3]) : "r"(addr))

__device__ __forceinline__ void mma16816(float* d, const uint32_t* a, const uint32_t* b) {
    asm volatile(
        "mma.sync.aligned.m16n8k16.row.col.f32.bf16.bf16.f32 "
        "{%0,%1,%2,%3}, {%4,%5,%6,%7}, {%8,%9}, {%0,%1,%2,%3};"
        : "+f"(d[0]), "+f"(d[1]), "+f"(d[2]), "+f"(d[3])
        : "r"(a[0]), "r"(a[1]), "r"(a[2]), "r"(a[3]), "r"(b[0]), "r"(b[1]));
}

__device__ __forceinline__ void mma16816h(float* d, const uint32_t* a, const uint32_t* b) {
    asm volatile(
        "mma.sync.aligned.m16n8k16.row.col.f32.f16.f16.f32 "
        "{%0,%1,%2,%3}, {%4,%5,%6,%7}, {%8,%9}, {%0,%1,%2,%3};"
        : "+f"(d[0]), "+f"(d[1]), "+f"(d[2]), "+f"(d[3])
        : "r"(a[0]), "r"(a[1]), "r"(a[2]), "r"(a[3]), "r"(b[0]), "r"(b[1]));
}

// packed f32x2 ops (FFMA2 — sm_100-family base ISA, PTX 8.6+)
typedef unsigned long long ull;
__device__ __forceinline__ ull fma2(ull a, ull b, ull c) {
    ull d; asm("fma.rn.f32x2 %0, %1, %2, %3;" : "=l"(d) : "l"(a), "l"(b), "l"(c)); return d;
}
__device__ __forceinline__ ull mul2(ull a, ull b) {
    ull d; asm("mul.rn.f32x2 %0, %1, %2;" : "=l"(d) : "l"(a), "l"(b)); return d;
}
__device__ __forceinline__ ull pack2(float x, float y) {
    ull r; asm("mov.b64 %0, {%1,%2};" : "=l"(r) : "f"(x), "f"(y)); return r;
}
__device__ __forceinline__ void unpack2(ull p, float& x, float& y) {
    asm("mov.b64 {%0,%1}, %2;" : "=f"(x), "=f"(y) : "l"(p));
}

// ---------------- splits ----------------
__device__ __forceinline__ void split4_bf16(float4 x, uint2& H, uint2& L) {
    __nv_bfloat162 h01 = __floats2bfloat162_rn(x.x, x.y);
    __nv_bfloat162 h23 = __floats2bfloat162_rn(x.z, x.w);
    float2 f01 = __bfloat1622float2(h01);
    float2 f23 = __bfloat1622float2(h23);
    __nv_bfloat162 l01 = __floats2bfloat162_rn(x.x - f01.x, x.y - f01.y);
    __nv_bfloat162 l23 = __floats2bfloat162_rn(x.z - f23.x, x.w - f23.y);
    H.x = *reinterpret_cast<unsigned int*>(&h01);
    H.y = *reinterpret_cast<unsigned int*>(&h23);
    L.x = *reinterpret_cast<unsigned int*>(&l01);
    L.y = *reinterpret_cast<unsigned int*>(&l23);
}

__device__ __forceinline__ uint2 pack4_f16(float4 x) {
    __half2 h01 = __floats2half2_rn(x.x, x.y);
    __half2 h23 = __floats2half2_rn(x.z, x.w);
    uint2 H;
    H.x = *reinterpret_cast<unsigned int*>(&h01);
    H.y = *reinterpret_cast<unsigned int*>(&h23);
    return H;
}

// acts: y=0 query (bf16 split), y=1 key_ (bf16 split), y=2 value (fp16 single)
__global__ void __launch_bounds__(256) split_acts_kernel(
    const float4* __restrict__ s0, const float4* __restrict__ s1, const float4* __restrict__ s2,
    uint2* __restrict__ hi, uint2* __restrict__ lo, int n4)
{
    int i = blockIdx.x * blockDim.x + threadIdx.x;
    if (i >= n4) return;
    int which = blockIdx.y;
    if (which < 2) {
        uint2 H, L;
        split4_bf16(which == 0 ? s0[i] : s1[i], H, L);
        hi[(size_t)which * n4 + i] = H;
        lo[(size_t)which * n4 + i] = L;
    } else {
        hi[(size_t)2 * n4 + i] = pack4_f16(s2[i]);
    }
}

// weights: y=0 Wq / y=1 Wk bf16 split; y=2 Wv / y=3 Wo fp16 single (hi only)
__global__ void __launch_bounds__(256) split_w_kernel(
    const float4* __restrict__ s0, const float4* __restrict__ s1,
    const float4* __restrict__ s2, const float4* __restrict__ s3,
    uint2* __restrict__ hi, uint2* __restrict__ lo, int n4)
{
    int i = blockIdx.x * blockDim.x + threadIdx.x;
    if (i >= n4) return;
    int which = blockIdx.y;
    if (which < 2) {
        uint2 H, L;
        split4_bf16(which == 0 ? s0[i] : s1[i], H, L);
        hi[(size_t)which * n4 + i] = H;
        lo[(size_t)which * n4 + i] = L;
    } else {
        hi[(size_t)which * n4 + i] = pack4_f16(which == 2 ? s2[i] : s3[i]);
    }
}

// ================= bf16x3 GEMM (GBK64, 1 CTA/SM) — R9 config ==============
#define GBM 128
#define GBN 128
#define GBK 64
#define KDIM DMODEL
#define NCHUNK (KDIM/GBK)      // 16
#define STAGE_BYTES 65536      // Ah 16K | Al 16K | Bh 16K | Bl 16K
#define A_HI 0
#define A_LO 16384
#define B_HI 32768
#define B_LO 49152
#define NSTAGE 3
#define GSMEM_TOTAL (NSTAGE*STAGE_BYTES)   // 196608

__global__ void __launch_bounds__(256, 1) gemm_bf16x3(
    const __nv_bfloat16* __restrict__ Ah, const __nv_bfloat16* __restrict__ Al,
    const __nv_bfloat16* __restrict__ Wh, const __nv_bfloat16* __restrict__ Wl,
    const float* __restrict__ bias, float* __restrict__ C)
{
    extern __shared__ char smem[];
    const uint32_t sb = smem_u32(smem);
    const int tid = threadIdx.x;
    const int m0 = blockIdx.y * GBM;
    const int n0 = blockIdx.x * GBN;

    const int l  = tid & 31;
    const int w  = tid >> 5;
    const int wm = (w & 3) * 32;
    const int wn = (w >> 2) * 64;

    const int rowA  = (l & 7) + ((l >> 3) & 1) * 8;
    const int kselA = (l >> 4) & 1;
    const int rowB  = (l & 7) + ((l >> 4) & 1) * 8;
    const int kselB = (l >> 3) & 1;

    float acc[2][8][4];
#pragma unroll
    for (int a = 0; a < 2; a++)
#pragma unroll
        for (int b = 0; b < 8; b++)
#pragma unroll
            for (int c = 0; c < 4; c++) acc[a][b][c] = 0.0f;

    auto load_chunk = [&](int st, int c) {
        uint32_t base = sb + st * STAGE_BYTES;
        int k0 = c * GBK;
#pragma unroll
        for (int it = 0; it < 4; it++) {
            int idx = tid + it * 256;
            int r  = idx >> 3;
            int ch = idx & 7;
            uint32_t sw = (uint32_t)(r * 128 + ((ch ^ (r & 7)) * 16));
            size_t gA = (size_t)(m0 + r) * KDIM + k0 + ch * 8;
            size_t gB = (size_t)(n0 + r) * KDIM + k0 + ch * 8;
            CP_ASYNC16(base + A_HI + sw, Ah + gA);
            CP_ASYNC16(base + A_LO + sw, Al + gA);
            CP_ASYNC16(base + B_HI + sw, Wh + gB);
            CP_ASYNC16(base + B_LO + sw, Wl + gB);
        }
    };

    uint32_t a_h[2][2][4], a_l[2][2][4], b_h[2][4][4], b_l[2][4][4];

    auto load_step = [&](uint32_t base, int s, int buf) {
#pragma unroll
        for (int mt = 0; mt < 2; mt++) {
            int row = wm + mt * 16 + rowA;
            int ch  = (s * 2 + kselA) ^ (row & 7);
            uint32_t off = (uint32_t)(row * 128 + ch * 16);
            LDSM_X4(a_h[buf][mt], base + A_HI + off);
            LDSM_X4(a_l[buf][mt], base + A_LO + off);
        }
#pragma unroll
        for (int ng = 0; ng < 4; ng++) {
            int row = wn + ng * 16 + rowB;
            int ch  = (s * 2 + kselB) ^ (row & 7);
            uint32_t off = (uint32_t)(row * 128 + ch * 16);
            LDSM_X4(b_h[buf][ng], base + B_HI + off);
            LDSM_X4(b_l[buf][ng], base + B_LO + off);
        }
    };

    auto mma_step = [&](int buf) {
#pragma unroll
        for (int p = 0; p < 3; p++) {
#pragma unroll
            for (int mt = 0; mt < 2; mt++) {
#pragma unroll
                for (int ng = 0; ng < 4; ng++) {
                    const uint32_t* A = (p == 2) ? a_l[buf][mt] : a_h[buf][mt];
                    const uint32_t* B = (p == 1) ? b_l[buf][ng] : b_h[buf][ng];
                    mma16816(acc[mt][ng * 2 + 0], A, &B[0]);
                    mma16816(acc[mt][ng * 2 + 1], A, &B[2]);
                }
            }
        }
    };

    load_chunk(0, 0); CP_COMMIT();
    load_chunk(1, 1); CP_COMMIT();

    for (int c = 0; c < NCHUNK; c++) {
        int st = c % NSTAGE;
        uint32_t base = sb + st * STAGE_BYTES;
        if (c + 2 < NCHUNK) { CP_WAIT(1); } else { CP_WAIT(0); }
        __syncthreads();
        if (c + 2 < NCHUNK) {
            load_chunk((c + 2) % NSTAGE, c + 2); CP_COMMIT();
        }
        load_step(base, 0, 0);
#pragma unroll
        for (int s = 0; s < 4; s++) {
            if (s < 3) load_step(base, s + 1, (s + 1) & 1);
            mma_step(s & 1);
        }
    }

    const int g  = l >> 2;
    const int tg = l & 3;
#pragma unroll
    for (int mt = 0; mt < 2; mt++) {
#pragma unroll
        for (int nt = 0; nt < 8; nt++) {
            int n = n0 + wn + nt * 8 + tg * 2;
            float bx = bias[n], by = bias[n + 1];
            int mA = m0 + wm + mt * 16 + g;
            float2 lo = make_float2(acc[mt][nt][0] + bx, acc[mt][nt][1] + by);
            float2 hi = make_float2(acc[mt][nt][2] + bx, acc[mt][nt][3] + by);
            *(float2*)(C + (size_t)mA * DMODEL + n)       = lo;
            *(float2*)(C + (size_t)(mA + 8) * DMODEL + n) = hi;
        }
    }
}

// ================= fp16x1 GEMM: C = A @ W^T + bias (V/O projections) ======
#define H1STAGE_BYTES 32768    // A 16K | B 16K
#define H1_A 0
#define H1_B 16384
#define H1SMEM_TOTAL (NSTAGE*H1STAGE_BYTES)  // 98304

__global__ void __launch_bounds__(256, 1) gemm_fp16x1(
    const __half* __restrict__ A, const __half* __restrict__ W,
    const float* __restrict__ bias, float* __restrict__ C)
{
    extern __shared__ char smem[];
    const uint32_t sb = smem_u32(smem);
    const int tid = threadIdx.x;
    const int m0 = blockIdx.y * GBM;
    const int n0 = blockIdx.x * GBN;

    const int l  = tid & 31;
    const int w  = tid >> 5;
    const int wm = (w & 3) * 32;
    const int wn = (w >> 2) * 64;

    const int rowA  = (l & 7) + ((l >> 3) & 1) * 8;
    const int kselA = (l >> 4) & 1;
    const int rowB  = (l & 7) + ((l >> 4) & 1) * 8;
    const int kselB = (l >> 3) & 1;

    float acc[2][8][4];
#pragma unroll
    for (int a = 0; a < 2; a++)
#pragma unroll
        for (int b = 0; b < 8; b++)
#pragma unroll
            for (int c = 0; c < 4; c++) acc[a][b][c] = 0.0f;

    auto load_chunk = [&](int st, int c) {
        uint32_t base = sb + st * H1STAGE_BYTES;
        int k0 = c * GBK;
#pragma unroll
        for (int it = 0; it < 4; it++) {
            int idx = tid + it * 256;
            int r  = idx >> 3;
            int ch = idx & 7;
            uint32_t sw = (uint32_t)(r * 128 + ((ch ^ (r & 7)) * 16));
            size_t gA = (size_t)(m0 + r) * KDIM + k0 + ch * 8;
            size_t gB = (size_t)(n0 + r) * KDIM + k0 + ch * 8;
            CP_ASYNC16(base + H1_A + sw, A + gA);
            CP_ASYNC16(base + H1_B + sw, W + gB);
        }
    };

    load_chunk(0, 0); CP_COMMIT();
    load_chunk(1, 1); CP_COMMIT();

    uint32_t ra[2][4], rb[4][4];

    for (int c = 0; c < NCHUNK; c++) {
        int st = c % NSTAGE;
        uint32_t base = sb + st * H1STAGE_BYTES;
        if (c + 2 < NCHUNK) { CP_WAIT(1); } else { CP_WAIT(0); }
        __syncthreads();
        if (c + 2 < NCHUNK) {
            load_chunk((c + 2) % NSTAGE, c + 2); CP_COMMIT();
        }
#pragma unroll
        for (int s = 0; s < 4; s++) {
#pragma unroll
            for (int mt = 0; mt < 2; mt++) {
                int row = wm + mt * 16 + rowA;
                int ch  = (s * 2 + kselA) ^ (row & 7);
                LDSM_X4(ra[mt], base + H1_A + (uint32_t)(row * 128 + ch * 16));
            }
#pragma unroll
            for (int ng = 0; ng < 4; ng++) {
                int row = wn + ng * 16 + rowB;
                int ch  = (s * 2 + kselB) ^ (row & 7);
                LDSM_X4(rb[ng], base + H1_B + (uint32_t)(row * 128 + ch * 16));
            }
#pragma unroll
            for (int mt = 0; mt < 2; mt++)
#pragma unroll
                for (int ng = 0; ng < 4; ng++) {
                    mma16816h(acc[mt][ng * 2 + 0], ra[mt], &rb[ng][0]);
                    mma16816h(acc[mt][ng * 2 + 1], ra[mt], &rb[ng][2]);
                }
        }
    }

    const int g  = l >> 2;
    const int tg = l & 3;
#pragma unroll
    for (int mt = 0; mt < 2; mt++) {
#pragma unroll
        for (int nt = 0; nt < 8; nt++) {
            int n = n0 + wn + nt * 8 + tg * 2;
            float bx = bias[n], by = bias[n + 1];
            int mA = m0 + wm + mt * 16 + g;
            float2 lo = make_float2(acc[mt][nt][0] + bx, acc[mt][nt][1] + by);
            float2 hi = make_float2(acc[mt][nt][2] + bx, acc[mt][nt][3] + by);
            *(float2*)(C + (size_t)mA * DMODEL + n)       = lo;
            *(float2*)(C + (size_t)(mA + 8) * DMODEL + n) = hi;
        }
    }
}

// ---------------- per-token attention v3: packed f32x2 FMA -----------------
// One warp per token; lane owns rows l and l+32. k stored TRANSPOSED in smem
// (kT[h][j], stride 66 floats) so score j-pairs are f32x2-adjacent; v row-major.
#define KT_STRIDE 66
#define KT_FLOATS (NHEAD * KT_STRIDE)      // 1056
__global__ __launch_bounds__(128) void attn_per_token(
    const float* __restrict__ q, const float* __restrict__ k,
    const float* __restrict__ v, __half* __restrict__ ao)
{
    const int w = threadIdx.x >> 5;
    const int l = threadIdx.x & 31;
    const int t = blockIdx.x * 4 + w;

    __shared__ float skT[4][KT_FLOATS];
    __shared__ float sv [4][DMODEL];

    float* skTw = skT[w];
    float* svw  = sv[w];

    // load k (transposed scatter) and v (straight)
    const float4* kt4 = (const float4*)(k + (size_t)t * DMODEL);
    const float4* vt4 = (const float4*)(v + (size_t)t * DMODEL);
#pragma unroll
    for (int f = l; f < 256; f += 32) {
        float4 kk = kt4[f];
        int d = f * 4;
        int j = d >> 4, h0 = d & 15;       // 4 consecutive h, same j
        skTw[(h0 + 0) * KT_STRIDE + j] = kk.x;
        skTw[(h0 + 1) * KT_STRIDE + j] = kk.y;
        skTw[(h0 + 2) * KT_STRIDE + j] = kk.z;
        skTw[(h0 + 3) * KT_STRIDE + j] = kk.w;
        ((float4*)svw)[f] = vt4[f];
    }
    __syncwarp();

    // q rows l, l+32, pre-scaled by 32, packed as (q,q) broadcast pairs
    ull qp0[NHEAD], qp1[NHEAD];
    const float* qt0 = q + (size_t)t * DMODEL + l * NHEAD;
    const float* qt1 = q + (size_t)t * DMODEL + (l + 32) * NHEAD;
#pragma unroll
    for (int h = 0; h < NHEAD; h++) {
        float a = qt0[h] * 32.0f;
        float b = qt1[h] * 32.0f;
        qp0[h] = pack2(a, a);
        qp1[h] = pack2(b, b);
    }

    float m0 = -1e30f, m1 = -1e30f, s0 = 0.f, s1 = 0.f;
    ull o0[8], o1[8];
#pragma unroll
    for (int e = 0; e < 8; e++) { o0[e] = 0ull; o1[e] = 0ull; }

#pragma unroll
    for (int jc = 0; jc < 4; jc++) {
        float sA[16], sB[16];
        float c0 = -1e30f, c1 = -1e30f;
        // scores for 8 j-pairs via f32x2
#pragma unroll
        for (int jp = 0; jp < 8; jp++) {
            int P2 = (jc * 8 + jp) * 2;    // even column index
            ull a0 = 0ull, a1 = 0ull;
#pragma unroll
            for (int h = 0; h < NHEAD; h++) {
                ull kp = *(const ull*)(skTw + h * KT_STRIDE + P2);
                a0 = fma2(qp0[h], kp, a0);
                a1 = fma2(qp1[h], kp, a1);
            }
            unpack2(a0, sA[jp * 2], sA[jp * 2 + 1]);
            unpack2(a1, sB[jp * 2], sB[jp * 2 + 1]);
            c0 = fmaxf(c0, fmaxf(sA[jp * 2], sA[jp * 2 + 1]));
            c1 = fmaxf(c1, fmaxf(sB[jp * 2], sB[jp * 2 + 1]));
        }
        float n0 = fmaxf(m0, c0), n1 = fmaxf(m1, c1);
        float r0 = __expf(m0 - n0), r1 = __expf(m1 - n1);
        s0 *= r0; s1 *= r1;
        ull rr0 = pack2(r0, r0), rr1 = pack2(r1, r1);
#pragma unroll
        for (int e = 0; e < 8; e++) {
            o0[e] = mul2(rr0, o0[e]);
            o1[e] = mul2(rr1, o1[e]);
        }
#pragma unroll
        for (int jj = 0; jj < 16; jj++) {
            int j = jc * 16 + jj;
            float p0 = __expf(sA[jj] - n0);
            float p1 = __expf(sB[jj] - n1);
            s0 += p0; s1 += p1;
            ull pp0 = pack2(p0, p0), pp1 = pack2(p1, p1);
            const ull* vrow = (const ull*)(svw + j * NHEAD);
#pragma unroll
            for (int e = 0; e < 8; e++) {
                ull vp = vrow[e];
                o0[e] = fma2(pp0, vp, o0[e]);
                o1[e] = fma2(pp1, vp, o1[e]);
            }
        }
        m0 = n0; m1 = n1;
    }

    const float i0 = 1.0f / s0;
    const float i1 = 1.0f / s1;
    uint32_t h0[8], h1[8];
#pragma unroll
    for (int e = 0; e < 8; e++) {
        float x0, y0, x1, y1;
        unpack2(o0[e], x0, y0);
        unpack2(o1[e], x1, y1);
        __half2 a = __floats2half2_rn(x0 * i0, y0 * i0);
        __half2 b = __floats2half2_rn(x1 * i1, y1 * i1);
        h0[e] = *reinterpret_cast<uint32_t*>(&a);
        h1[e] = *reinterpret_cast<uint32_t*>(&b);
    }
    size_t ob0 = (size_t)t * DMODEL + l * NHEAD;
    size_t ob1 = (size_t)t * DMODEL + (l + 32) * NHEAD;
    *(uint4*)(ao + ob0)     = make_uint4(h0[0], h0[1], h0[2], h0[3]);
    *(uint4*)(ao + ob0 + 8) = make_uint4(h0[4], h0[5], h0[6], h0[7]);
    *(uint4*)(ao + ob1)     = make_uint4(h1[0], h1[1], h1[2], h1[3]);
    *(uint4*)(ao + ob1 + 8) = make_uint4(h1[4], h1[5], h1[6], h1[7]);
}

// ---------------- launch ----------------
extern "C" void kernel_launch(void* const* d_in, const int* in_sizes, int n_in,
                              void* d_out, int out_size)
{
    const float* query = (const float*)d_in[0];
    const float* key_  = (const float*)d_in[1];
    const float* value = (const float*)d_in[2];
    const float* Wq    = (const float*)d_in[3];
    const float* bq    = (const float*)d_in[4];
    const float* Wk    = (const float*)d_in[5];
    const float* bk    = (const float*)d_in[6];
    const float* Wv    = (const float*)d_in[7];
    const float* bv    = (const float*)d_in[8];
    const float* Wo    = (const float*)d_in[9];
    const float* bo    = (const float*)d_in[10];
    float* out = (float*)d_out;

    float *q, *k, *v;
    __nv_bfloat16 *xh, *xl, *wh, *wl;
    cudaGetSymbolAddress((void**)&q,  g_q);
    cudaGetSymbolAddress((void**)&k,  g_k);
    cudaGetSymbolAddress((void**)&v,  g_v);
    cudaGetSymbolAddress((void**)&xh, g_xh);
    cudaGetSymbolAddress((void**)&xl, g_xl);
    cudaGetSymbolAddress((void**)&wh, g_wh);
    cudaGetSymbolAddress((void**)&wl, g_wl);

    cudaFuncSetAttribute(gemm_bf16x3, cudaFuncAttributeMaxDynamicSharedMemorySize, GSMEM_TOTAL);
    cudaFuncSetAttribute(gemm_fp16x1, cudaFuncAttributeMaxDynamicSharedMemorySize, H1SMEM_TOTAL);

    const int nAct4 = (int)(ACT_ELEMS / 4);
    const int nW4   = (int)(W_ELEMS / 4);
    dim3 sgA((nAct4 + 255) / 256, 3);
    dim3 sgW((nW4 + 255) / 256, 4);
    dim3 ggrid(DMODEL / GBN, MTOK / GBM);   // (8, 128)

    split_acts_kernel<<<sgA, 256>>>((const float4*)query, (const float4*)key_,
                                    (const float4*)value, (uint2*)xh, (uint2*)xl, nAct4);
    split_w_kernel<<<sgW, 256>>>((const float4*)Wq, (const float4*)Wk,
                                 (const float4*)Wv, (const float4*)Wo,
                                 (uint2*)wh, (uint2*)wl, nW4);

    // Q, K projections: bf16x3 (score-critical precision)
    gemm_bf16x3<<<ggrid, 256, GSMEM_TOTAL>>>(xh,             xl,             wh,           wl,           bq, q);
    gemm_bf16x3<<<ggrid, 256, GSMEM_TOTAL>>>(xh + ACT_ELEMS, xl + ACT_ELEMS, wh + W_ELEMS, wl + W_ELEMS, bk, k);
    // V projection: fp16 single product
    gemm_fp16x1<<<ggrid, 256, H1SMEM_TOTAL>>>((const __half*)(xh + 2 * ACT_ELEMS),
                                              (const __half*)(wh + 2 * W_ELEMS), bv, v);

    // attention: one warp per token, f32x2 math, writes ao fp16 into slice 0 of xh
    attn_per_token<<<MTOK / 4, 128>>>(q, k, v, (__half*)xh);

    // O projection: fp16 single product
    gemm_fp16x1<<<ggrid, 256, H1SMEM_TOTAL>>>((const __half*)xh,
                                              (const __half*)(wh + 3 * W_ELEMS), bo, out);
}

// round 16
// speedup vs baseline: 1.0555x; 1.0524x over previous
#include <cuda_runtime.h>
#include <cuda_bf16.h>
#include <cuda_fp16.h>
#include <math.h>
#include <stdint.h>

// ---------------- problem constants ----------------
#define BATCH 4
#define SEQ 4096
#define DMODEL 1024
#define NHEAD 16
#define DH 64
#define MTOK (BATCH*SEQ)   // 16384
#define ACT_ELEMS ((size_t)MTOK * DMODEL)
#define W_ELEMS   ((size_t)DMODEL * DMODEL)

// ---------------- scratch (__device__ globals; allocation-free rule) ------
__device__ float g_q [ACT_ELEMS];
__device__ float g_k [ACT_ELEMS];
__device__ __half g_vh[ACT_ELEMS];              // V projection output, fp16
// slice 0: Q acts bf16-hi (later reused as ao fp16), 1: K acts bf16-hi, 2: V acts fp16
__device__ __nv_bfloat16 g_xh[3 * ACT_ELEMS];
__device__ __nv_bfloat16 g_xl[3 * ACT_ELEMS];   // lo splits for slices 0,1 only
// slice 0: Wq-hi bf16, 1: Wk-hi bf16, 2: Wv fp16 (single), 3: Wo fp16 (single)
__device__ __nv_bfloat16 g_wh[4 * W_ELEMS];
__device__ __nv_bfloat16 g_wl[4 * W_ELEMS];     // lo used only for slices 0,1

// ---------------- small PTX helpers (base ISA + sm_100-family f32x2) ------
__device__ __forceinline__ uint32_t smem_u32(const void* p) {
    uint32_t a;
    asm("{ .reg .u64 t; cvta.to.shared.u64 t, %1; cvt.u32.u64 %0, t; }" : "=r"(a) : "l"(p));
    return a;
}

#define CP_ASYNC16(saddr, gptr) \
    asm volatile("cp.async.cg.shared.global [%0], [%1], 16;" :: "r"((uint32_t)(saddr)), "l"(gptr))
#define CP_COMMIT() asm volatile("cp.async.commit_group;" ::: "memory")
#define CP_WAIT(n)  asm volatile("cp.async.wait_group %0;" :: "n"(n) : "memory")

#define LDSM_X4(r, addr) \
    asm volatile("ldmatrix.sync.aligned.m8n8.x4.shared.b16 {%0,%1,%2,%3}, [%4];" \
        : "=r"((r)[0]), "=r"((r)[1]), "=r"((r)[2]), "=r"((r)[3]) : "r"(addr))

__device__ __forceinline__ void mma16816(float* d, const uint32_t* a, const uint32_t* b) {
    asm volatile(
        "mma.sync.aligned.m16n8k16.row.col.f32.bf16.bf16.f32 "
        "{%0,%1,%2,%3}, {%4,%5,%6,%7}, {%8,%9}, {%0,%1,%2,%3};"
        : "+f"(d[0]), "+f"(d[1]), "+f"(d[2]), "+f"(d[3])
        : "r"(a[0]), "r"(a[1]), "r"(a[2]), "r"(a[3]), "r"(b[0]), "r"(b[1]));
}

__device__ __forceinline__ void mma16816h(float* d, const uint32_t* a, const uint32_t* b) {
    asm volatile(
        "mma.sync.aligned.m16n8k16.row.col.f32.f16.f16.f32 "
        "{%0,%1,%2,%3}, {%4,%5,%6,%7}, {%8,%9}, {%0,%1,%2,%3};"
        : "+f"(d[0]), "+f"(d[1]), "+f"(d[2]), "+f"(d[3])
        : "r"(a[0]), "r"(a[1]), "r"(a[2]), "r"(a[3]), "r"(b[0]), "r"(b[1]));
}

// packed f32x2 ops (FFMA2 — sm_100-family base ISA)
typedef unsigned long long ull;
__device__ __forceinline__ ull fma2(ull a, ull b, ull c) {
    ull d; asm("fma.rn.f32x2 %0, %1, %2, %3;" : "=l"(d) : "l"(a), "l"(b), "l"(c)); return d;
}
__device__ __forceinline__ ull mul2(ull a, ull b) {
    ull d; asm("mul.rn.f32x2 %0, %1, %2;" : "=l"(d) : "l"(a), "l"(b)); return d;
}
__device__ __forceinline__ ull pack2(float x, float y) {
    ull r; asm("mov.b64 %0, {%1,%2};" : "=l"(r) : "f"(x), "f"(y)); return r;
}
__device__ __forceinline__ void unpack2(ull p, float& x, float& y) {
    asm("mov.b64 {%0,%1}, %2;" : "=f"(x), "=f"(y) : "l"(p));
}

// ---------------- splits ----------------
__device__ __forceinline__ void split4_bf16(float4 x, uint2& H, uint2& L) {
    __nv_bfloat162 h01 = __floats2bfloat162_rn(x.x, x.y);
    __nv_bfloat162 h23 = __floats2bfloat162_rn(x.z, x.w);
    float2 f01 = __bfloat1622float2(h01);
    float2 f23 = __bfloat1622float2(h23);
    __nv_bfloat162 l01 = __floats2bfloat162_rn(x.x - f01.x, x.y - f01.y);
    __nv_bfloat162 l23 = __floats2bfloat162_rn(x.z - f23.x, x.w - f23.y);
    H.x = *reinterpret_cast<unsigned int*>(&h01);
    H.y = *reinterpret_cast<unsigned int*>(&h23);
    L.x = *reinterpret_cast<unsigned int*>(&l01);
    L.y = *reinterpret_cast<unsigned int*>(&l23);
}

__device__ __forceinline__ uint2 pack4_f16(float4 x) {
    __half2 h01 = __floats2half2_rn(x.x, x.y);
    __half2 h23 = __floats2half2_rn(x.z, x.w);
    uint2 H;
    H.x = *reinterpret_cast<unsigned int*>(&h01);
    H.y = *reinterpret_cast<unsigned int*>(&h23);
    return H;
}

// acts: y=0 query (bf16 split), y=1 key_ (bf16 split), y=2 value (fp16 single)
__global__ void __launch_bounds__(256) split_acts_kernel(
    const float4* __restrict__ s0, const float4* __restrict__ s1, const float4* __restrict__ s2,
    uint2* __restrict__ hi, uint2* __restrict__ lo, int n4)
{
    int i = blockIdx.x * blockDim.x + threadIdx.x;
    if (i >= n4) return;
    int which = blockIdx.y;
    if (which < 2) {
        uint2 H, L;
        split4_bf16(which == 0 ? s0[i] : s1[i], H, L);
        hi[(size_t)which * n4 + i] = H;
        lo[(size_t)which * n4 + i] = L;
    } else {
        hi[(size_t)2 * n4 + i] = pack4_f16(s2[i]);
    }
}

// weights: y=0 Wq / y=1 Wk bf16 split; y=2 Wv / y=3 Wo fp16 single (hi only)
__global__ void __launch_bounds__(256) split_w_kernel(
    const float4* __restrict__ s0, const float4* __restrict__ s1,
    const float4* __restrict__ s2, const float4* __restrict__ s3,
    uint2* __restrict__ hi, uint2* __restrict__ lo, int n4)
{
    int i = blockIdx.x * blockDim.x + threadIdx.x;
    if (i >= n4) return;
    int which = blockIdx.y;
    if (which < 2) {
        uint2 H, L;
        split4_bf16(which == 0 ? s0[i] : s1[i], H, L);
        hi[(size_t)which * n4 + i] = H;
        lo[(size_t)which * n4 + i] = L;
    } else {
        hi[(size_t)which * n4 + i] = pack4_f16(which == 2 ? s2[i] : s3[i]);
    }
}

// ================= bf16x3 GEMM (GBK64, 1 CTA/SM) — pinned config ==========
#define GBM 128
#define GBN 128
#define GBK 64
#define KDIM DMODEL
#define NCHUNK (KDIM/GBK)      // 16
#define STAGE_BYTES 65536      // Ah 16K | Al 16K | Bh 16K | Bl 16K
#define A_HI 0
#define A_LO 16384
#define B_HI 32768
#define B_LO 49152
#define NSTAGE 3
#define GSMEM_TOTAL (NSTAGE*STAGE_BYTES)   // 196608

__global__ void __launch_bounds__(256, 1) gemm_bf16x3(
    const __nv_bfloat16* __restrict__ Ah, const __nv_bfloat16* __restrict__ Al,
    const __nv_bfloat16* __restrict__ Wh, const __nv_bfloat16* __restrict__ Wl,
    const float* __restrict__ bias, float* __restrict__ C)
{
    extern __shared__ char smem[];
    const uint32_t sb = smem_u32(smem);
    const int tid = threadIdx.x;
    const int m0 = blockIdx.y * GBM;
    const int n0 = blockIdx.x * GBN;

    const int l  = tid & 31;
    const int w  = tid >> 5;
    const int wm = (w & 3) * 32;
    const int wn = (w >> 2) * 64;

    const int rowA  = (l & 7) + ((l >> 3) & 1) * 8;
    const int kselA = (l >> 4) & 1;
    const int rowB  = (l & 7) + ((l >> 4) & 1) * 8;
    const int kselB = (l >> 3) & 1;

    float acc[2][8][4];
#pragma unroll
    for (int a = 0; a < 2; a++)
#pragma unroll
        for (int b = 0; b < 8; b++)
#pragma unroll
            for (int c = 0; c < 4; c++) acc[a][b][c] = 0.0f;

    auto load_chunk = [&](int st, int c) {
        uint32_t base = sb + st * STAGE_BYTES;
        int k0 = c * GBK;
#pragma unroll
        for (int it = 0; it < 4; it++) {
            int idx = tid + it * 256;
            int r  = idx >> 3;
            int ch = idx & 7;
            uint32_t sw = (uint32_t)(r * 128 + ((ch ^ (r & 7)) * 16));
            size_t gA = (size_t)(m0 + r) * KDIM + k0 + ch * 8;
            size_t gB = (size_t)(n0 + r) * KDIM + k0 + ch * 8;
            CP_ASYNC16(base + A_HI + sw, Ah + gA);
            CP_ASYNC16(base + A_LO + sw, Al + gA);
            CP_ASYNC16(base + B_HI + sw, Wh + gB);
            CP_ASYNC16(base + B_LO + sw, Wl + gB);
        }
    };

    uint32_t a_h[2][2][4], a_l[2][2][4], b_h[2][4][4], b_l[2][4][4];

    auto load_step = [&](uint32_t base, int s, int buf) {
#pragma unroll
        for (int mt = 0; mt < 2; mt++) {
            int row = wm + mt * 16 + rowA;
            int ch  = (s * 2 + kselA) ^ (row & 7);
            uint32_t off = (uint32_t)(row * 128 + ch * 16);
            LDSM_X4(a_h[buf][mt], base + A_HI + off);
            LDSM_X4(a_l[buf][mt], base + A_LO + off);
        }
#pragma unroll
        for (int ng = 0; ng < 4; ng++) {
            int row = wn + ng * 16 + rowB;
            int ch  = (s * 2 + kselB) ^ (row & 7);
            uint32_t off = (uint32_t)(row * 128 + ch * 16);
            LDSM_X4(b_h[buf][ng], base + B_HI + off);
            LDSM_X4(b_l[buf][ng], base + B_LO + off);
        }
    };

    auto mma_step = [&](int buf) {
#pragma unroll
        for (int p = 0; p < 3; p++) {
#pragma unroll
            for (int mt = 0; mt < 2; mt++) {
#pragma unroll
                for (int ng = 0; ng < 4; ng++) {
                    const uint32_t* A = (p == 2) ? a_l[buf][mt] : a_h[buf][mt];
                    const uint32_t* B = (p == 1) ? b_l[buf][ng] : b_h[buf][ng];
                    mma16816(acc[mt][ng * 2 + 0], A, &B[0]);
                    mma16816(acc[mt][ng * 2 + 1], A, &B[2]);
                }
            }
        }
    };

    load_chunk(0, 0); CP_COMMIT();
    load_chunk(1, 1); CP_COMMIT();

    for (int c = 0; c < NCHUNK; c++) {
        int st = c % NSTAGE;
        uint32_t base = sb + st * STAGE_BYTES;
        if (c + 2 < NCHUNK) { CP_WAIT(1); } else { CP_WAIT(0); }
        __syncthreads();
        if (c + 2 < NCHUNK) {
            load_chunk((c + 2) % NSTAGE, c + 2); CP_COMMIT();
        }
        load_step(base, 0, 0);
#pragma unroll
        for (int s = 0; s < 4; s++) {
            if (s < 3) load_step(base, s + 1, (s + 1) & 1);
            mma_step(s & 1);
        }
    }

    const int g  = l >> 2;
    const int tg = l & 3;
#pragma unroll
    for (int mt = 0; mt < 2; mt++) {
#pragma unroll
        for (int nt = 0; nt < 8; nt++) {
            int n = n0 + wn + nt * 8 + tg * 2;
            float bx = bias[n], by = bias[n + 1];
            int mA = m0 + wm + mt * 16 + g;
            float2 lo = make_float2(acc[mt][nt][0] + bx, acc[mt][nt][1] + by);
            float2 hi = make_float2(acc[mt][nt][2] + bx, acc[mt][nt][3] + by);
            *(float2*)(C + (size_t)mA * DMODEL + n)       = lo;
            *(float2*)(C + (size_t)(mA + 8) * DMODEL + n) = hi;
        }
    }
}

// ================= fp16x1 GEMM, 2 CTAs/SM ==================================
// C = A @ W^T + bias. OUT_HALF=1 -> write __half, else fp32.
#define H1STAGE_BYTES 32768    // A 16K | B 16K
#define H1_A 0
#define H1_B 16384
#define H1SMEM_TOTAL (NSTAGE*H1STAGE_BYTES)  // 98304

template <int OUT_HALF>
__global__ void __launch_bounds__(256, 2) gemm_fp16x1(
    const __half* __restrict__ A, const __half* __restrict__ W,
    const float* __restrict__ bias, void* __restrict__ Cv)
{
    extern __shared__ char smem[];
    const uint32_t sb = smem_u32(smem);
    const int tid = threadIdx.x;
    const int m0 = blockIdx.y * GBM;
    const int n0 = blockIdx.x * GBN;

    const int l  = tid & 31;
    const int w  = tid >> 5;
    const int wm = (w & 3) * 32;
    const int wn = (w >> 2) * 64;

    const int rowA  = (l & 7) + ((l >> 3) & 1) * 8;
    const int kselA = (l >> 4) & 1;
    const int rowB  = (l & 7) + ((l >> 4) & 1) * 8;
    const int kselB = (l >> 3) & 1;

    float acc[2][8][4];
#pragma unroll
    for (int a = 0; a < 2; a++)
#pragma unroll
        for (int b = 0; b < 8; b++)
#pragma unroll
            for (int c = 0; c < 4; c++) acc[a][b][c] = 0.0f;

    auto load_chunk = [&](int st, int c) {
        uint32_t base = sb + st * H1STAGE_BYTES;
        int k0 = c * GBK;
#pragma unroll
        for (int it = 0; it < 4; it++) {
            int idx = tid + it * 256;
            int r  = idx >> 3;
            int ch = idx & 7;
            uint32_t sw = (uint32_t)(r * 128 + ((ch ^ (r & 7)) * 16));
            size_t gA = (size_t)(m0 + r) * KDIM + k0 + ch * 8;
            size_t gB = (size_t)(n0 + r) * KDIM + k0 + ch * 8;
            CP_ASYNC16(base + H1_A + sw, A + gA);
            CP_ASYNC16(base + H1_B + sw, W + gB);
        }
    };

    load_chunk(0, 0); CP_COMMIT();
    load_chunk(1, 1); CP_COMMIT();

    uint32_t ra[2][4], rb[4][4];

    for (int c = 0; c < NCHUNK; c++) {
        int st = c % NSTAGE;
        uint32_t base = sb + st * H1STAGE_BYTES;
        if (c + 2 < NCHUNK) { CP_WAIT(1); } else { CP_WAIT(0); }
        __syncthreads();
        if (c + 2 < NCHUNK) {
            load_chunk((c + 2) % NSTAGE, c + 2); CP_COMMIT();
        }
#pragma unroll
        for (int s = 0; s < 4; s++) {
#pragma unroll
            for (int mt = 0; mt < 2; mt++) {
                int row = wm + mt * 16 + rowA;
                int ch  = (s * 2 + kselA) ^ (row & 7);
                LDSM_X4(ra[mt], base + H1_A + (uint32_t)(row * 128 + ch * 16));
            }
#pragma unroll
            for (int ng = 0; ng < 4; ng++) {
                int row = wn + ng * 16 + rowB;
                int ch  = (s * 2 + kselB) ^ (row & 7);
                LDSM_X4(rb[ng], base + H1_B + (uint32_t)(row * 128 + ch * 16));
            }
#pragma unroll
            for (int mt = 0; mt < 2; mt++)
#pragma unroll
                for (int ng = 0; ng < 4; ng++) {
                    mma16816h(acc[mt][ng * 2 + 0], ra[mt], &rb[ng][0]);
                    mma16816h(acc[mt][ng * 2 + 1], ra[mt], &rb[ng][2]);
                }
        }
    }

    const int g  = l >> 2;
    const int tg = l & 3;
#pragma unroll
    for (int mt = 0; mt < 2; mt++) {
#pragma unroll
        for (int nt = 0; nt < 8; nt++) {
            int n = n0 + wn + nt * 8 + tg * 2;
            float bx = bias[n], by = bias[n + 1];
            int mA = m0 + wm + mt * 16 + g;
            float lx = acc[mt][nt][0] + bx, ly = acc[mt][nt][1] + by;
            float hx = acc[mt][nt][2] + bx, hy = acc[mt][nt][3] + by;
            if (OUT_HALF) {
                __half* C = (__half*)Cv;
                __half2 lo2 = __floats2half2_rn(lx, ly);
                __half2 hi2 = __floats2half2_rn(hx, hy);
                *(__half2*)(C + (size_t)mA * DMODEL + n)       = lo2;
                *(__half2*)(C + (size_t)(mA + 8) * DMODEL + n) = hi2;
            } else {
                float* C = (float*)Cv;
                *(float2*)(C + (size_t)mA * DMODEL + n)       = make_float2(lx, ly);
                *(float2*)(C + (size_t)(mA + 8) * DMODEL + n) = make_float2(hx, hy);
            }
        }
    }
}

// ---------------- per-token attention v3: packed f32x2 FMA, fp16 v --------
#define KT_STRIDE 66
#define KT_FLOATS (NHEAD * KT_STRIDE)      // 1056
__global__ __launch_bounds__(128) void attn_per_token(
    const float* __restrict__ q, const float* __restrict__ k,
    const __half* __restrict__ v, __half* __restrict__ ao)
{
    const int w = threadIdx.x >> 5;
    const int l = threadIdx.x & 31;
    const int t = blockIdx.x * 4 + w;

    __shared__ float skT[4][KT_FLOATS];
    __shared__ float sv [4][DMODEL];

    float* skTw = skT[w];
    float* svw  = sv[w];

    // load k (transposed scatter, fp32) and v (fp16 -> fp32 convert)
    const float4* kt4 = (const float4*)(k + (size_t)t * DMODEL);
    const uint2*  vt2 = (const uint2*)(v + (size_t)t * DMODEL);   // 4 halves per uint2
#pragma unroll
    for (int f = l; f < 256; f += 32) {
        float4 kk = kt4[f];
        int d = f * 4;
        int j = d >> 4, h0 = d & 15;
        skTw[(h0 + 0) * KT_STRIDE + j] = kk.x;
        skTw[(h0 + 1) * KT_STRIDE + j] = kk.y;
        skTw[(h0 + 2) * KT_STRIDE + j] = kk.z;
        skTw[(h0 + 3) * KT_STRIDE + j] = kk.w;
        uint2 vp = vt2[f];
        __half2 v01 = *reinterpret_cast<__half2*>(&vp.x);
        __half2 v23 = *reinterpret_cast<__half2*>(&vp.y);
        float2 f01 = __half22float2(v01);
        float2 f23 = __half22float2(v23);
        float4 vv = make_float4(f01.x, f01.y, f23.x, f23.y);
        ((float4*)svw)[f] = vv;
    }
    __syncwarp();

    // q rows l, l+32, pre-scaled by 32, packed as (q,q) broadcast pairs
    ull qp0[NHEAD], qp1[NHEAD];
    const float* qt0 = q + (size_t)t * DMODEL + l * NHEAD;
    const float* qt1 = q + (size_t)t * DMODEL + (l + 32) * NHEAD;
#pragma unroll
    for (int h = 0; h < NHEAD; h++) {
        float a = qt0[h] * 32.0f;
        float b = qt1[h] * 32.0f;
        qp0[h] = pack2(a, a);
        qp1[h] = pack2(b, b);
    }

    float m0 = -1e30f, m1 = -1e30f, s0 = 0.f, s1 = 0.f;
    ull o0[8], o1[8];
#pragma unroll
    for (int e = 0; e < 8; e++) { o0[e] = 0ull; o1[e] = 0ull; }

#pragma unroll
    for (int jc = 0; jc < 4; jc++) {
        float sA[16], sB[16];
        float c0 = -1e30f, c1 = -1e30f;
#pragma unroll
        for (int jp = 0; jp < 8; jp++) {
            int P2 = (jc * 8 + jp) * 2;
            ull a0 = 0ull, a1 = 0ull;
#pragma unroll
            for (int h = 0; h < NHEAD; h++) {
                ull kp = *(const ull*)(skTw + h * KT_STRIDE + P2);
                a0 = fma2(qp0[h], kp, a0);
                a1 = fma2(qp1[h], kp, a1);
            }
            unpack2(a0, sA[jp * 2], sA[jp * 2 + 1]);
            unpack2(a1, sB[jp * 2], sB[jp * 2 + 1]);
            c0 = fmaxf(c0, fmaxf(sA[jp * 2], sA[jp * 2 + 1]));
            c1 = fmaxf(c1, fmaxf(sB[jp * 2], sB[jp * 2 + 1]));
        }
        float n0 = fmaxf(m0, c0), n1 = fmaxf(m1, c1);
        float r0 = __expf(m0 - n0), r1 = __expf(m1 - n1);
        s0 *= r0; s1 *= r1;
        ull rr0 = pack2(r0, r0), rr1 = pack2(r1, r1);
#pragma unroll
        for (int e = 0; e < 8; e++) {
            o0[e] = mul2(rr0, o0[e]);
            o1[e] = mul2(rr1, o1[e]);
        }
#pragma unroll
        for (int jj = 0; jj < 16; jj++) {
            int j = jc * 16 + jj;
            float p0 = __expf(sA[jj] - n0);
            float p1 = __expf(sB[jj] - n1);
            s0 += p0; s1 += p1;
            ull pp0 = pack2(p0, p0), pp1 = pack2(p1, p1);
            const ull* vrow = (const ull*)(svw + j * NHEAD);
#pragma unroll
            for (int e = 0; e < 8; e++) {
                ull vp = vrow[e];
                o0[e] = fma2(pp0, vp, o0[e]);
                o1[e] = fma2(pp1, vp, o1[e]);
            }
        }
        m0 = n0; m1 = n1;
    }

    const float i0 = 1.0f / s0;
    const float i1 = 1.0f / s1;
    uint32_t h0[8], h1[8];
#pragma unroll
    for (int e = 0; e < 8; e++) {
        float x0, y0, x1, y1;
        unpack2(o0[e], x0, y0);
        unpack2(o1[e], x1, y1);
        __half2 a = __floats2half2_rn(x0 * i0, y0 * i0);
        __half2 b = __floats2half2_rn(x1 * i1, y1 * i1);
        h0[e] = *reinterpret_cast<uint32_t*>(&a);
        h1[e] = *reinterpret_cast<uint32_t*>(&b);
    }
    size_t ob0 = (size_t)t * DMODEL + l * NHEAD;
    size_t ob1 = (size_t)t * DMODEL + (l + 32) * NHEAD;
    *(uint4*)(ao + ob0)     = make_uint4(h0[0], h0[1], h0[2], h0[3]);
    *(uint4*)(ao + ob0 + 8) = make_uint4(h0[4], h0[5], h0[6], h0[7]);
    *(uint4*)(ao + ob1)     = make_uint4(h1[0], h1[1], h1[2], h1[3]);
    *(uint4*)(ao + ob1 + 8) = make_uint4(h1[4], h1[5], h1[6], h1[7]);
}

// ---------------- launch ----------------
extern "C" void kernel_launch(void* const* d_in, const int* in_sizes, int n_in,
                              void* d_out, int out_size)
{
    const float* query = (const float*)d_in[0];
    const float* key_  = (const float*)d_in[1];
    const float* value = (const float*)d_in[2];
    const float* Wq    = (const float*)d_in[3];
    const float* bq    = (const float*)d_in[4];
    const float* Wk    = (const float*)d_in[5];
    const float* bk    = (const float*)d_in[6];
    const float* Wv    = (const float*)d_in[7];
    const float* bv    = (const float*)d_in[8];
    const float* Wo    = (const float*)d_in[9];
    const float* bo    = (const float*)d_in[10];
    float* out = (float*)d_out;

    float *q, *k;
    __half *vh;
    __nv_bfloat16 *xh, *xl, *wh, *wl;
    cudaGetSymbolAddress((void**)&q,  g_q);
    cudaGetSymbolAddress((void**)&k,  g_k);
    cudaGetSymbolAddress((void**)&vh, g_vh);
    cudaGetSymbolAddress((void**)&xh, g_xh);
    cudaGetSymbolAddress((void**)&xl, g_xl);
    cudaGetSymbolAddress((void**)&wh, g_wh);
    cudaGetSymbolAddress((void**)&wl, g_wl);

    cudaFuncSetAttribute(gemm_bf16x3,   cudaFuncAttributeMaxDynamicSharedMemorySize, GSMEM_TOTAL);
    cudaFuncSetAttribute(gemm_fp16x1<1>, cudaFuncAttributeMaxDynamicSharedMemorySize, H1SMEM_TOTAL);
    cudaFuncSetAttribute(gemm_fp16x1<0>, cudaFuncAttributeMaxDynamicSharedMemorySize, H1SMEM_TOTAL);

    const int nAct4 = (int)(ACT_ELEMS / 4);
    const int nW4   = (int)(W_ELEMS / 4);
    dim3 sgA((nAct4 + 255) / 256, 3);
    dim3 sgW((nW4 + 255) / 256, 4);
    dim3 ggrid(DMODEL / GBN, MTOK / GBM);   // (8, 128)

    split_acts_kernel<<<sgA, 256>>>((const float4*)query, (const float4*)key_,
                                    (const float4*)value, (uint2*)xh, (uint2*)xl, nAct4);
    split_w_kernel<<<sgW, 256>>>((const float4*)Wq, (const float4*)Wk,
                                 (const float4*)Wv, (const float4*)Wo,
                                 (uint2*)wh, (uint2*)wl, nW4);

    // Q, K projections: bf16x3 (score-critical precision)
    gemm_bf16x3<<<ggrid, 256, GSMEM_TOTAL>>>(xh,             xl,             wh,           wl,           bq, q);
    gemm_bf16x3<<<ggrid, 256, GSMEM_TOTAL>>>(xh + ACT_ELEMS, xl + ACT_ELEMS, wh + W_ELEMS, wl + W_ELEMS, bk, k);
    // V projection: fp16 single product, writes fp16 directly
    gemm_fp16x1<1><<<ggrid, 256, H1SMEM_TOTAL>>>((const __half*)(xh + 2 * ACT_ELEMS),
                                                 (const __half*)(wh + 2 * W_ELEMS), bv, vh);

    // attention: one warp per token, f32x2 math, fp16 v in, ao fp16 out (slice 0 of xh)
    attn_per_token<<<MTOK / 4, 128>>>(q, k, vh, (__half*)xh);

    // O projection: fp16 single product, fp32 out
    gemm_fp16x1<0><<<ggrid, 256, H1SMEM_TOTAL>>>((const __half*)xh,
                                                 (const __half*)(wh + 3 * W_ELEMS), bo, out);
}

// round 17
// speedup vs baseline: 1.0701x; 1.0138x over previous
#include <cuda_runtime.h>
#include <cuda_bf16.h>
#include <cuda_fp16.h>
#include <math.h>
#include <stdint.h>

// ---------------- problem constants ----------------
#define BATCH 4
#define SEQ 4096
#define DMODEL 1024
#define NHEAD 16
#define DH 64
#define MTOK (BATCH*SEQ)   // 16384
#define ACT_ELEMS ((size_t)MTOK * DMODEL)
#define W_ELEMS   ((size_t)DMODEL * DMODEL)

// ---------------- scratch (__device__ globals; allocation-free rule) ------
__device__ float g_q [ACT_ELEMS];
__device__ float g_k [ACT_ELEMS];
__device__ __half g_vh[ACT_ELEMS];              // V projection output, fp16
__device__ __nv_bfloat16 g_xh[3 * ACT_ELEMS];
__device__ __nv_bfloat16 g_xl[3 * ACT_ELEMS];   // lo splits for slices 0,1 only
__device__ __nv_bfloat16 g_wh[4 * W_ELEMS];
__device__ __nv_bfloat16 g_wl[4 * W_ELEMS];     // lo used only for slices 0,1

// ---------------- small PTX helpers (base ISA + sm_100-family f32x2) ------
__device__ __forceinline__ uint32_t smem_u32(const void* p) {
    uint32_t a;
    asm("{ .reg .u64 t; cvta.to.shared.u64 t, %1; cvt.u32.u64 %0, t; }" : "=r"(a) : "l"(p));
    return a;
}

#define CP_ASYNC16(saddr, gptr) \
    asm volatile("cp.async.cg.shared.global [%0], [%1], 16;" :: "r"((uint32_t)(saddr)), "l"(gptr))
#define CP_COMMIT() asm volatile("cp.async.commit_group;" ::: "memory")
#define CP_WAIT(n)  asm volatile("cp.async.wait_group %0;" :: "n"(n) : "memory")

#define LDSM_X4(r, addr) \
    asm volatile("ldmatrix.sync.aligned.m8n8.x4.shared.b16 {%0,%1,%2,%3}, [%4];" \
        : "=r"((r)[0]), "=r"((r)[1]), "=r"((r)[2]), "=r"((r)[3]) : "r"(addr))

__device__ __forceinline__ void mma16816(float* d, const uint32_t* a, const uint32_t* b) {
    asm volatile(
        "mma.sync.aligned.m16n8k16.row.col.f32.bf16.bf16.f32 "
        "{%0,%1,%2,%3}, {%4,%5,%6,%7}, {%8,%9}, {%0,%1,%2,%3};"
        : "+f"(d[0]), "+f"(d[1]), "+f"(d[2]), "+f"(d[3])
        : "r"(a[0]), "r"(a[1]), "r"(a[2]), "r"(a[3]), "r"(b[0]), "r"(b[1]));
}

__device__ __forceinline__ void mma16816h(float* d, const uint32_t* a, const uint32_t* b) {
    asm volatile(
        "mma.sync.aligned.m16n8k16.row.col.f32.f16.f16.f32 "
        "{%0,%1,%2,%3}, {%4,%5,%6,%7}, {%8,%9}, {%0,%1,%2,%3};"
        : "+f"(d[0]), "+f"(d[1]), "+f"(d[2]), "+f"(d[3])
        : "r"(a[0]), "r"(a[1]), "r"(a[2]), "r"(a[3]), "r"(b[0]), "r"(b[1]));
}

// packed f32x2 ops (FFMA2 — sm_100-family base ISA)
typedef unsigned long long ull;
__device__ __forceinline__ ull fma2(ull a, ull b, ull c) {
    ull d; asm("fma.rn.f32x2 %0, %1, %2, %3;" : "=l"(d) : "l"(a), "l"(b), "l"(c)); return d;
}
__device__ __forceinline__ ull mul2(ull a, ull b) {
    ull d; asm("mul.rn.f32x2 %0, %1, %2;" : "=l"(d) : "l"(a), "l"(b)); return d;
}
__device__ __forceinline__ ull add2(ull a, ull b) {
    ull d; asm("add.rn.f32x2 %0, %1, %2;" : "=l"(d) : "l"(a), "l"(b)); return d;
}
__device__ __forceinline__ ull pack2(float x, float y) {
    ull r; asm("mov.b64 %0, {%1,%2};" : "=l"(r) : "f"(x), "f"(y)); return r;
}
__device__ __forceinline__ void unpack2(ull p, float& x, float& y) {
    asm("mov.b64 {%0,%1}, %2;" : "=f"(x), "=f"(y) : "l"(p));
}

// ---------------- splits ----------------
__device__ __forceinline__ void split4_bf16(float4 x, uint2& H, uint2& L) {
    __nv_bfloat162 h01 = __floats2bfloat162_rn(x.x, x.y);
    __nv_bfloat162 h23 = __floats2bfloat162_rn(x.z, x.w);
    float2 f01 = __bfloat1622float2(h01);
    float2 f23 = __bfloat1622float2(h23);
    __nv_bfloat162 l01 = __floats2bfloat162_rn(x.x - f01.x, x.y - f01.y);
    __nv_bfloat162 l23 = __floats2bfloat162_rn(x.z - f23.x, x.w - f23.y);
    H.x = *reinterpret_cast<unsigned int*>(&h01);
    H.y = *reinterpret_cast<unsigned int*>(&h23);
    L.x = *reinterpret_cast<unsigned int*>(&l01);
    L.y = *reinterpret_cast<unsigned int*>(&l23);
}

__device__ __forceinline__ uint2 pack4_f16(float4 x) {
    __half2 h01 = __floats2half2_rn(x.x, x.y);
    __half2 h23 = __floats2half2_rn(x.z, x.w);
    uint2 H;
    H.x = *reinterpret_cast<unsigned int*>(&h01);
    H.y = *reinterpret_cast<unsigned int*>(&h23);
    return H;
}

// acts: y=0 query (bf16 split), y=1 key_ (bf16 split), y=2 value (fp16 single)
__global__ void __launch_bounds__(256) split_acts_kernel(
    const float4* __restrict__ s0, const float4* __restrict__ s1, const float4* __restrict__ s2,
    uint2* __restrict__ hi, uint2* __restrict__ lo, int n4)
{
    int i = blockIdx.x * blockDim.x + threadIdx.x;
    if (i >= n4) return;
    int which = blockIdx.y;
    if (which < 2) {
        uint2 H, L;
        split4_bf16(which == 0 ? s0[i] : s1[i], H, L);
        hi[(size_t)which * n4 + i] = H;
        lo[(size_t)which * n4 + i] = L;
    } else {
        hi[(size_t)2 * n4 + i] = pack4_f16(s2[i]);
    }
}

// weights: y=0 Wq / y=1 Wk bf16 split; y=2 Wv / y=3 Wo fp16 single (hi only)
__global__ void __launch_bounds__(256) split_w_kernel(
    const float4* __restrict__ s0, const float4* __restrict__ s1,
    const float4* __restrict__ s2, const float4* __restrict__ s3,
    uint2* __restrict__ hi, uint2* __restrict__ lo, int n4)
{
    int i = blockIdx.x * blockDim.x + threadIdx.x;
    if (i >= n4) return;
    int which = blockIdx.y;
    if (which < 2) {
        uint2 H, L;
        split4_bf16(which == 0 ? s0[i] : s1[i], H, L);
        hi[(size_t)which * n4 + i] = H;
        lo[(size_t)which * n4 + i] = L;
    } else {
        hi[(size_t)which * n4 + i] = pack4_f16(which == 2 ? s2[i] : s3[i]);
    }
}

// ================= bf16x3 GEMM (GBK64, 1 CTA/SM) — pinned config ==========
#define GBM 128
#define GBN 128
#define GBK 64
#define KDIM DMODEL
#define NCHUNK (KDIM/GBK)      // 16
#define STAGE_BYTES 65536      // Ah 16K | Al 16K | Bh 16K | Bl 16K
#define A_HI 0
#define A_LO 16384
#define B_HI 32768
#define B_LO 49152
#define NSTAGE 3
#define GSMEM_TOTAL (NSTAGE*STAGE_BYTES)   // 196608

__global__ void __launch_bounds__(256, 1) gemm_bf16x3(
    const __nv_bfloat16* __restrict__ Ah, const __nv_bfloat16* __restrict__ Al,
    const __nv_bfloat16* __restrict__ Wh, const __nv_bfloat16* __restrict__ Wl,
    const float* __restrict__ bias, float* __restrict__ C)
{
    extern __shared__ char smem[];
    const uint32_t sb = smem_u32(smem);
    const int tid = threadIdx.x;
    const int m0 = blockIdx.y * GBM;
    const int n0 = blockIdx.x * GBN;

    const int l  = tid & 31;
    const int w  = tid >> 5;
    const int wm = (w & 3) * 32;
    const int wn = (w >> 2) * 64;

    const int rowA  = (l & 7) + ((l >> 3) & 1) * 8;
    const int kselA = (l >> 4) & 1;
    const int rowB  = (l & 7) + ((l >> 4) & 1) * 8;
    const int kselB = (l >> 3) & 1;

    float acc[2][8][4];
#pragma unroll
    for (int a = 0; a < 2; a++)
#pragma unroll
        for (int b = 0; b < 8; b++)
#pragma unroll
            for (int c = 0; c < 4; c++) acc[a][b][c] = 0.0f;

    auto load_chunk = [&](int st, int c) {
        uint32_t base = sb + st * STAGE_BYTES;
        int k0 = c * GBK;
#pragma unroll
        for (int it = 0; it < 4; it++) {
            int idx = tid + it * 256;
            int r  = idx >> 3;
            int ch = idx & 7;
            uint32_t sw = (uint32_t)(r * 128 + ((ch ^ (r & 7)) * 16));
            size_t gA = (size_t)(m0 + r) * KDIM + k0 + ch * 8;
            size_t gB = (size_t)(n0 + r) * KDIM + k0 + ch * 8;
            CP_ASYNC16(base + A_HI + sw, Ah + gA);
            CP_ASYNC16(base + A_LO + sw, Al + gA);
            CP_ASYNC16(base + B_HI + sw, Wh + gB);
            CP_ASYNC16(base + B_LO + sw, Wl + gB);
        }
    };

    uint32_t a_h[2][2][4], a_l[2][2][4], b_h[2][4][4], b_l[2][4][4];

    auto load_step = [&](uint32_t base, int s, int buf) {
#pragma unroll
        for (int mt = 0; mt < 2; mt++) {
            int row = wm + mt * 16 + rowA;
            int ch  = (s * 2 + kselA) ^ (row & 7);
            uint32_t off = (uint32_t)(row * 128 + ch * 16);
            LDSM_X4(a_h[buf][mt], base + A_HI + off);
            LDSM_X4(a_l[buf][mt], base + A_LO + off);
        }
#pragma unroll
        for (int ng = 0; ng < 4; ng++) {
            int row = wn + ng * 16 + rowB;
            int ch  = (s * 2 + kselB) ^ (row & 7);
            uint32_t off = (uint32_t)(row * 128 + ch * 16);
            LDSM_X4(b_h[buf][ng], base + B_HI + off);
            LDSM_X4(b_l[buf][ng], base + B_LO + off);
        }
    };

    auto mma_step = [&](int buf) {
#pragma unroll
        for (int p = 0; p < 3; p++) {
#pragma unroll
            for (int mt = 0; mt < 2; mt++) {
#pragma unroll
                for (int ng = 0; ng < 4; ng++) {
                    const uint32_t* A = (p == 2) ? a_l[buf][mt] : a_h[buf][mt];
                    const uint32_t* B = (p == 1) ? b_l[buf][ng] : b_h[buf][ng];
                    mma16816(acc[mt][ng * 2 + 0], A, &B[0]);
                    mma16816(acc[mt][ng * 2 + 1], A, &B[2]);
                }
            }
        }
    };

    load_chunk(0, 0); CP_COMMIT();
    load_chunk(1, 1); CP_COMMIT();

    for (int c = 0; c < NCHUNK; c++) {
        int st = c % NSTAGE;
        uint32_t base = sb + st * STAGE_BYTES;
        if (c + 2 < NCHUNK) { CP_WAIT(1); } else { CP_WAIT(0); }
        __syncthreads();
        if (c + 2 < NCHUNK) {
            load_chunk((c + 2) % NSTAGE, c + 2); CP_COMMIT();
        }
        load_step(base, 0, 0);
#pragma unroll
        for (int s = 0; s < 4; s++) {
            if (s < 3) load_step(base, s + 1, (s + 1) & 1);
            mma_step(s & 1);
        }
    }

    const int g  = l >> 2;
    const int tg = l & 3;
#pragma unroll
    for (int mt = 0; mt < 2; mt++) {
#pragma unroll
        for (int nt = 0; nt < 8; nt++) {
            int n = n0 + wn + nt * 8 + tg * 2;
            float bx = bias[n], by = bias[n + 1];
            int mA = m0 + wm + mt * 16 + g;
            float2 lo = make_float2(acc[mt][nt][0] + bx, acc[mt][nt][1] + by);
            float2 hi = make_float2(acc[mt][nt][2] + bx, acc[mt][nt][3] + by);
            *(float2*)(C + (size_t)mA * DMODEL + n)       = lo;
            *(float2*)(C + (size_t)(mA + 8) * DMODEL + n) = hi;
        }
    }
}

// ================= fp16x1 GEMM, 2 CTAs/SM ==================================
#define H1STAGE_BYTES 32768    // A 16K | B 16K
#define H1_A 0
#define H1_B 16384
#define H1SMEM_TOTAL (NSTAGE*H1STAGE_BYTES)  // 98304

template <int OUT_HALF>
__global__ void __launch_bounds__(256, 2) gemm_fp16x1(
    const __half* __restrict__ A, const __half* __restrict__ W,
    const float* __restrict__ bias, void* __restrict__ Cv)
{
    extern __shared__ char smem[];
    const uint32_t sb = smem_u32(smem);
    const int tid = threadIdx.x;
    const int m0 = blockIdx.y * GBM;
    const int n0 = blockIdx.x * GBN;

    const int l  = tid & 31;
    const int w  = tid >> 5;
    const int wm = (w & 3) * 32;
    const int wn = (w >> 2) * 64;

    const int rowA  = (l & 7) + ((l >> 3) & 1) * 8;
    const int kselA = (l >> 4) & 1;
    const int rowB  = (l & 7) + ((l >> 4) & 1) * 8;
    const int kselB = (l >> 3) & 1;

    float acc[2][8][4];
#pragma unroll
    for (int a = 0; a < 2; a++)
#pragma unroll
        for (int b = 0; b < 8; b++)
#pragma unroll
            for (int c = 0; c < 4; c++) acc[a][b][c] = 0.0f;

    auto load_chunk = [&](int st, int c) {
        uint32_t base = sb + st * H1STAGE_BYTES;
        int k0 = c * GBK;
#pragma unroll
        for (int it = 0; it < 4; it++) {
            int idx = tid + it * 256;
            int r  = idx >> 3;
            int ch = idx & 7;
            uint32_t sw = (uint32_t)(r * 128 + ((ch ^ (r & 7)) * 16));
            size_t gA = (size_t)(m0 + r) * KDIM + k0 + ch * 8;
            size_t gB = (size_t)(n0 + r) * KDIM + k0 + ch * 8;
            CP_ASYNC16(base + H1_A + sw, A + gA);
            CP_ASYNC16(base + H1_B + sw, W + gB);
        }
    };

    load_chunk(0, 0); CP_COMMIT();
    load_chunk(1, 1); CP_COMMIT();

    uint32_t ra[2][4], rb[4][4];

    for (int c = 0; c < NCHUNK; c++) {
        int st = c % NSTAGE;
        uint32_t base = sb + st * H1STAGE_BYTES;
        if (c + 2 < NCHUNK) { CP_WAIT(1); } else { CP_WAIT(0); }
        __syncthreads();
        if (c + 2 < NCHUNK) {
            load_chunk((c + 2) % NSTAGE, c + 2); CP_COMMIT();
        }
#pragma unroll
        for (int s = 0; s < 4; s++) {
#pragma unroll
            for (int mt = 0; mt < 2; mt++) {
                int row = wm + mt * 16 + rowA;
                int ch  = (s * 2 + kselA) ^ (row & 7);
                LDSM_X4(ra[mt], base + H1_A + (uint32_t)(row * 128 + ch * 16));
            }
#pragma unroll
            for (int ng = 0; ng < 4; ng++) {
                int row = wn + ng * 16 + rowB;
                int ch  = (s * 2 + kselB) ^ (row & 7);
                LDSM_X4(rb[ng], base + H1_B + (uint32_t)(row * 128 + ch * 16));
            }
#pragma unroll
            for (int mt = 0; mt < 2; mt++)
#pragma unroll
                for (int ng = 0; ng < 4; ng++) {
                    mma16816h(acc[mt][ng * 2 + 0], ra[mt], &rb[ng][0]);
                    mma16816h(acc[mt][ng * 2 + 1], ra[mt], &rb[ng][2]);
                }
        }
    }

    const int g  = l >> 2;
    const int tg = l & 3;
#pragma unroll
    for (int mt = 0; mt < 2; mt++) {
#pragma unroll
        for (int nt = 0; nt < 8; nt++) {
            int n = n0 + wn + nt * 8 + tg * 2;
            float bx = bias[n], by = bias[n + 1];
            int mA = m0 + wm + mt * 16 + g;
            float lx = acc[mt][nt][0] + bx, ly = acc[mt][nt][1] + by;
            float hx = acc[mt][nt][2] + bx, hy = acc[mt][nt][3] + by;
            if (OUT_HALF) {
                __half* C = (__half*)Cv;
                __half2 lo2 = __floats2half2_rn(lx, ly);
                __half2 hi2 = __floats2half2_rn(hx, hy);
                *(__half2*)(C + (size_t)mA * DMODEL + n)       = lo2;
                *(__half2*)(C + (size_t)(mA + 8) * DMODEL + n) = hi2;
            } else {
                float* C = (float*)Cv;
                *(float2*)(C + (size_t)mA * DMODEL + n)       = make_float2(lx, ly);
                *(float2*)(C + (size_t)(mA + 8) * DMODEL + n) = make_float2(hx, hy);
            }
        }
    }
}

// ---------------- per-token attention v4: pair-major k, LDS.128 -----------
// One warp per token; lane owns rows l and l+32. k stored PAIR-MAJOR:
// kP[jp][h] = ull(k[2jp][h], k[2jp+1][h]) — rows of 16 ull = 128B, read as
// ulonglong2 (LDS.128, broadcast). v rows read as ulonglong2 too.
__global__ __launch_bounds__(128) void attn_per_token(
    const float* __restrict__ q, const float* __restrict__ k,
    const __half* __restrict__ v, __half* __restrict__ ao)
{
    const int w = threadIdx.x >> 5;
    const int l = threadIdx.x & 31;
    const int t = blockIdx.x * 4 + w;

    __shared__ float skP[4][1024];   // 32 jp x 16 h x 2 (pair) floats
    __shared__ float sv [4][DMODEL];

    float* skPw = skP[w];
    float* svw  = sv[w];

    // load k (pair-major scatter, fp32) and v (fp16 -> fp32 convert)
    const float4* kt4 = (const float4*)(k + (size_t)t * DMODEL);
    const uint2*  vt2 = (const uint2*)(v + (size_t)t * DMODEL);
#pragma unroll
    for (int f = l; f < 256; f += 32) {
        float4 kk = kt4[f];
        int d = f * 4;
        int j = d >> 4, h0 = d & 15;        // 4 consecutive h, same j
        float* kb = skPw + ((j >> 1) << 5) + (j & 1);   // jp*32 + parity
        kb[(h0 + 0) * 2] = kk.x;
        kb[(h0 + 1) * 2] = kk.y;
        kb[(h0 + 2) * 2] = kk.z;
        kb[(h0 + 3) * 2] = kk.w;
        uint2 vp = vt2[f];
        __half2 v01 = *reinterpret_cast<__half2*>(&vp.x);
        __half2 v23 = *reinterpret_cast<__half2*>(&vp.y);
        float2 f01 = __half22float2(v01);
        float2 f23 = __half22float2(v23);
        ((float4*)svw)[f] = make_float4(f01.x, f01.y, f23.x, f23.y);
    }
    __syncwarp();

    // q rows l, l+32, pre-scaled by 32, packed as (q,q) broadcast pairs
    ull qp0[NHEAD], qp1[NHEAD];
    const float* qt0 = q + (size_t)t * DMODEL + l * NHEAD;
    const float* qt1 = q + (size_t)t * DMODEL + (l + 32) * NHEAD;
#pragma unroll
    for (int h = 0; h < NHEAD; h++) {
        float a = qt0[h] * 32.0f;
        float b = qt1[h] * 32.0f;
        qp0[h] = pack2(a, a);
        qp1[h] = pack2(b, b);
    }

    float m0 = -1e30f, m1 = -1e30f, s0 = 0.f, s1 = 0.f;
    ull o0[8], o1[8];
#pragma unroll
    for (int e = 0; e < 8; e++) { o0[e] = 0ull; o1[e] = 0ull; }

#pragma unroll
    for (int jc = 0; jc < 4; jc++) {
        float sA[16], sB[16];
        float c0 = -1e30f, c1 = -1e30f;
#pragma unroll
        for (int jp8 = 0; jp8 < 8; jp8++) {
            int jp = jc * 8 + jp8;
            const ulonglong2* kr = (const ulonglong2*)(skPw + (jp << 5));
            ull ae = 0ull, ao_ = 0ull, be = 0ull, bo_ = 0ull;   // 2 chains/row
#pragma unroll
            for (int hh = 0; hh < 8; hh++) {
                ulonglong2 kk = kr[hh];                          // h=2hh, 2hh+1
                ae  = fma2(qp0[2 * hh + 0], kk.x, ae);
                ao_ = fma2(qp0[2 * hh + 1], kk.y, ao_);
                be  = fma2(qp1[2 * hh + 0], kk.x, be);
                bo_ = fma2(qp1[2 * hh + 1], kk.y, bo_);
            }
            ull a0 = add2(ae, ao_);
            ull a1 = add2(be, bo_);
            unpack2(a0, sA[jp8 * 2], sA[jp8 * 2 + 1]);
            unpack2(a1, sB[jp8 * 2], sB[jp8 * 2 + 1]);
            c0 = fmaxf(c0, fmaxf(sA[jp8 * 2], sA[jp8 * 2 + 1]));
            c1 = fmaxf(c1, fmaxf(sB[jp8 * 2], sB[jp8 * 2 + 1]));
        }
        float n0 = fmaxf(m0, c0), n1 = fmaxf(m1, c1);
        float r0 = __expf(m0 - n0), r1 = __expf(m1 - n1);
        s0 *= r0; s1 *= r1;
        ull rr0 = pack2(r0, r0), rr1 = pack2(r1, r1);
#pragma unroll
        for (int e = 0; e < 8; e++) {
            o0[e] = mul2(rr0, o0[e]);
            o1[e] = mul2(rr1, o1[e]);
        }
#pragma unroll
        for (int jj = 0; jj < 16; jj++) {
            int j = jc * 16 + jj;
            float p0 = __expf(sA[jj] - n0);
            float p1 = __expf(sB[jj] - n1);
            s0 += p0; s1 += p1;
            ull pp0 = pack2(p0, p0), pp1 = pack2(p1, p1);
            const ulonglong2* vr = (const ulonglong2*)(svw + j * NHEAD);
#pragma unroll
            for (int e2 = 0; e2 < 4; e2++) {
                ulonglong2 vp = vr[e2];                          // LDS.128
                o0[e2 * 2 + 0] = fma2(pp0, vp.x, o0[e2 * 2 + 0]);
                o0[e2 * 2 + 1] = fma2(pp0, vp.y, o0[e2 * 2 + 1]);
                o1[e2 * 2 + 0] = fma2(pp1, vp.x, o1[e2 * 2 + 0]);
                o1[e2 * 2 + 1] = fma2(pp1, vp.y, o1[e2 * 2 + 1]);
            }
        }
        m0 = n0; m1 = n1;
    }

    const float i0 = 1.0f / s0;
    const float i1 = 1.0f / s1;
    uint32_t h0[8], h1[8];
#pragma unroll
    for (int e = 0; e < 8; e++) {
        float x0, y0, x1, y1;
        unpack2(o0[e], x0, y0);
        unpack2(o1[e], x1, y1);
        __half2 a = __floats2half2_rn(x0 * i0, y0 * i0);
        __half2 b = __floats2half2_rn(x1 * i1, y1 * i1);
        h0[e] = *reinterpret_cast<uint32_t*>(&a);
        h1[e] = *reinterpret_cast<uint32_t*>(&b);
    }
    size_t ob0 = (size_t)t * DMODEL + l * NHEAD;
    size_t ob1 = (size_t)t * DMODEL + (l + 32) * NHEAD;
    *(uint4*)(ao + ob0)     = make_uint4(h0[0], h0[1], h0[2], h0[3]);
    *(uint4*)(ao + ob0 + 8) = make_uint4(h0[4], h0[5], h0[6], h0[7]);
    *(uint4*)(ao + ob1)     = make_uint4(h1[0], h1[1], h1[2], h1[3]);
    *(uint4*)(ao + ob1 + 8) = make_uint4(h1[4], h1[5], h1[6], h1[7]);
}

// ---------------- launch ----------------
extern "C" void kernel_launch(void* const* d_in, const int* in_sizes, int n_in,
                              void* d_out, int out_size)
{
    const float* query = (const float*)d_in[0];
    const float* key_  = (const float*)d_in[1];
    const float* value = (const float*)d_in[2];
    const float* Wq    = (const float*)d_in[3];
    const float* bq    = (const float*)d_in[4];
    const float* Wk    = (const float*)d_in[5];
    const float* bk    = (const float*)d_in[6];
    const float* Wv    = (const float*)d_in[7];
    const float* bv    = (const float*)d_in[8];
    const float* Wo    = (const float*)d_in[9];
    const float* bo    = (const float*)d_in[10];
    float* out = (float*)d_out;

    float *q, *k;
    __half *vh;
    __nv_bfloat16 *xh, *xl, *wh, *wl;
    cudaGetSymbolAddress((void**)&q,  g_q);
    cudaGetSymbolAddress((void**)&k,  g_k);
    cudaGetSymbolAddress((void**)&vh, g_vh);
    cudaGetSymbolAddress((void**)&xh, g_xh);
    cudaGetSymbolAddress((void**)&xl, g_xl);
    cudaGetSymbolAddress((void**)&wh, g_wh);
    cudaGetSymbolAddress((void**)&wl, g_wl);

    cudaFuncSetAttribute(gemm_bf16x3,    cudaFuncAttributeMaxDynamicSharedMemorySize, GSMEM_TOTAL);
    cudaFuncSetAttribute(gemm_fp16x1<1>, cudaFuncAttributeMaxDynamicSharedMemorySize, H1SMEM_TOTAL);
    cudaFuncSetAttribute(gemm_fp16x1<0>, cudaFuncAttributeMaxDynamicSharedMemorySize, H1SMEM_TOTAL);

    const int nAct4 = (int)(ACT_ELEMS / 4);
    const int nW4   = (int)(W_ELEMS / 4);
    dim3 sgA((nAct4 + 255) / 256, 3);
    dim3 sgW((nW4 + 255) / 256, 4);
    dim3 ggrid(DMODEL / GBN, MTOK / GBM);   // (8, 128)

    split_acts_kernel<<<sgA, 256>>>((const float4*)query, (const float4*)key_,
                                    (const float4*)value, (uint2*)xh, (uint2*)xl, nAct4);
    split_w_kernel<<<sgW, 256>>>((const float4*)Wq, (const float4*)Wk,
                                 (const float4*)Wv, (const float4*)Wo,
                                 (uint2*)wh, (uint2*)wl, nW4);

    // Q, K projections: bf16x3 (score-critical precision)
    gemm_bf16x3<<<ggrid, 256, GSMEM_TOTAL>>>(xh,             xl,             wh,           wl,           bq, q);
    gemm_bf16x3<<<ggrid, 256, GSMEM_TOTAL>>>(xh + ACT_ELEMS, xl + ACT_ELEMS, wh + W_ELEMS, wl + W_ELEMS, bk, k);
    // V projection: fp16 single product, writes fp16 directly
    gemm_fp16x1<1><<<ggrid, 256, H1SMEM_TOTAL>>>((const __half*)(xh + 2 * ACT_ELEMS),
                                                 (const __half*)(wh + 2 * W_ELEMS), bv, vh);

    // attention: one warp per token, pair-major k, LDS.128 reads
    attn_per_token<<<MTOK / 4, 128>>>(q, k, vh, (__half*)xh);

    // O projection: fp16 single product, fp32 out
    gemm_fp16x1<0><<<ggrid, 256, H1SMEM_TOTAL>>>((const __half*)xh,
                                                 (const __half*)(wh + 3 * W_ELEMS), bo, out);
}